// round 10
// baseline (speedup 1.0000x reference)
#include <cuda_runtime.h>
#include <math.h>

#define SEQ   2048
#define NH    32
#define HD    64
#define HIDD  2048
#define NB    2
#define NQKV  (3 * NH * HD)   // 6144
#define MROWS (NB * SEQ)      // 4096

// Scratch (static __device__ arrays per harness rules — no cudaMalloc anywhere)
__device__ float g_qkv[(size_t)MROWS * NQKV];          // [4096][6144] raw QKV
__device__ float g_Q[(size_t)NB * NH * SEQ * HD];      // [B,H,S,D], pre-scaled by 1/8
__device__ float g_K[(size_t)NB * NH * SEQ * HD];
__device__ float g_V[(size_t)NB * NH * SEQ * HD];
__device__ float g_attn[(size_t)MROWS * HIDD];         // [4096][2048]
__device__ int   g_mask_u8;                            // 1 = 1-byte bool, 0 = 4-byte words

// ---------------------------------------------------------------------------
// Detect the attention_mask element width. Bool serialized as 1-byte has 0x01
// bytes at intra-word positions >= 1 (random 0/1 bytes). int32 "1" is
// 01 00 00 00 and float32 "1.0" is 00 00 80 3F — neither ever has 0x01 at
// byte positions 1..3. Scan 1 MB (well within the smallest possible buffer).
// ---------------------------------------------------------------------------
__global__ void detect_mask_kernel(const unsigned char* __restrict__ m) {
    __shared__ int found;
    if (threadIdx.x == 0) found = 0;
    __syncthreads();
    const uint4* p = (const uint4*)m;
    int f = 0;
    for (int i = threadIdx.x; i < 65536; i += blockDim.x) {
        uint4 w = p[i];
        unsigned ws[4] = {w.x, w.y, w.z, w.w};
#pragma unroll
        for (int j = 0; j < 4; ++j) {
            unsigned v = ws[j];
            if (((v >> 8) & 0xFFu) == 1u || ((v >> 16) & 0xFFu) == 1u ||
                ((v >> 24) & 0xFFu) == 1u)
                f = 1;
        }
    }
    if (f) atomicOr(&found, 1);
    __syncthreads();
    if (threadIdx.x == 0) g_mask_u8 = found;
}

// ---------------------------------------------------------------------------
// C[m][n] = sum_k A[m][k] * B[n][k]   (NT GEMM, both operands K-major)
// 128x128 block tile, BK=8, 256 threads, 8x8 per-thread register tile.
// ---------------------------------------------------------------------------
__global__ __launch_bounds__(256, 2) void sgemm_nt(const float* __restrict__ A,
                                                   const float* __restrict__ B,
                                                   float* __restrict__ C,
                                                   int K, int N) {
    __shared__ float As[8][128];
    __shared__ float Bs[8][128];
    const int tid = threadIdx.x;
    const int m0 = blockIdx.y * 128;
    const int n0 = blockIdx.x * 128;
    const int lr = tid >> 1;
    const int lc = (tid & 1) << 2;
    const float* Ag = A + (size_t)(m0 + lr) * K + lc;
    const float* Bg = B + (size_t)(n0 + lr) * K + lc;
    const int ty = tid >> 4;
    const int tx = tid & 15;

    float acc[8][8];
#pragma unroll
    for (int i = 0; i < 8; ++i)
#pragma unroll
        for (int j = 0; j < 8; ++j) acc[i][j] = 0.f;

    for (int k0 = 0; k0 < K; k0 += 8) {
        float4 av = *(const float4*)(Ag + k0);
        float4 bv = *(const float4*)(Bg + k0);
        __syncthreads();
        As[lc + 0][lr] = av.x; As[lc + 1][lr] = av.y;
        As[lc + 2][lr] = av.z; As[lc + 3][lr] = av.w;
        Bs[lc + 0][lr] = bv.x; Bs[lc + 1][lr] = bv.y;
        Bs[lc + 2][lr] = bv.z; Bs[lc + 3][lr] = bv.w;
        __syncthreads();
#pragma unroll
        for (int kk = 0; kk < 8; ++kk) {
            float4 a0 = *(const float4*)&As[kk][ty << 2];
            float4 a1 = *(const float4*)&As[kk][64 + (ty << 2)];
            float4 b0 = *(const float4*)&Bs[kk][tx << 2];
            float4 b1 = *(const float4*)&Bs[kk][64 + (tx << 2)];
            float a[8] = {a0.x, a0.y, a0.z, a0.w, a1.x, a1.y, a1.z, a1.w};
            float bb[8] = {b0.x, b0.y, b0.z, b0.w, b1.x, b1.y, b1.z, b1.w};
#pragma unroll
            for (int i = 0; i < 8; ++i)
#pragma unroll
                for (int j = 0; j < 8; ++j)
                    acc[i][j] = fmaf(a[i], bb[j], acc[i][j]);
        }
    }
#pragma unroll
    for (int i = 0; i < 8; ++i) {
        int m = m0 + ((i < 4) ? (ty * 4 + i) : (64 + ty * 4 + i - 4));
        float4 c0 = make_float4(acc[i][0], acc[i][1], acc[i][2], acc[i][3]);
        float4 c1 = make_float4(acc[i][4], acc[i][5], acc[i][6], acc[i][7]);
        *(float4*)(C + (size_t)m * N + n0 + (tx << 2)) = c0;
        *(float4*)(C + (size_t)m * N + n0 + 64 + (tx << 2)) = c1;
    }
}

// ---------------------------------------------------------------------------
// Split raw QKV into Q/K/V [B,H,S,D]; apply RoPE to Q,K; fold 1/sqrt(D) into Q.
// Angle rounded to f32 exactly like the reference table (f32 pos * f32 invfreq),
// then sin/cos in double of that f32 angle for accuracy.
// ---------------------------------------------------------------------------
__global__ __launch_bounds__(256) void rope_scatter(const float* __restrict__ qkv,
                                                    const int* __restrict__ pos_ids) {
    int idx = blockIdx.x * blockDim.x + threadIdx.x;   // NB*SEQ*NH*32 threads
    int d = idx & 31;
    int h = (idx >> 5) & (NH - 1);
    int s = (idx >> 10) & (SEQ - 1);
    int b = idx >> 21;
    int pos = pos_ids[b * SEQ + s];

    const float* src = qkv + (size_t)(b * SEQ + s) * NQKV + h * (3 * HD);
    float q1 = src[d],       q2 = src[d + 32];
    float k1 = src[64 + d],  k2 = src[96 + d];
    float v1 = src[128 + d], v2 = src[160 + d];

    float invf = (float)pow(10000.0, -(double)d / 32.0);
    float t = (float)pos * invf;
    float sn = (float)sin((double)t);
    float cs = (float)cos((double)t);

    size_t dst = ((size_t)(b * NH + h) * SEQ + s) * HD;
    const float qs = 0.125f;   // 1/sqrt(64)
    g_Q[dst + d]      = (q1 * cs - q2 * sn) * qs;
    g_Q[dst + d + 32] = (q2 * cs + q1 * sn) * qs;
    g_K[dst + d]      = k1 * cs - k2 * sn;
    g_K[dst + d + 32] = k2 * cs + k1 * sn;
    g_V[dst + d]      = v1;
    g_V[dst + d + 32] = v2;
}

// ---------------------------------------------------------------------------
// Flash attention, fp32. One block per (b, h, 64-row q tile). 256 threads.
// S-tile 64x64 with 4x4 per-thread register tiles; online softmax; P in smem.
// Mask element width selected at runtime via g_mask_u8.
// ---------------------------------------------------------------------------
__global__ __launch_bounds__(256) void flash_attn(const unsigned char* __restrict__ mask,
                                                  float* __restrict__ attn) {
    extern __shared__ float sm[];
    float* Qt  = sm;               // [64 d][64 q]
    float* Kt  = Qt + 64 * 64;     // [64 d][64 k]
    float* Vs  = Kt + 64 * 64;     // [64 k][64 d]
    float* Ps  = Vs + 64 * 64;     // [64 q][64 k]
    float* red = Ps + 64 * 64;     // [64 q][16 tx]
    float* m_s = red + 64 * 16;    // running row max [64]
    float* l_s = m_s + 64;         // running row sum [64]
    float* c_s = l_s + 64;         // per-tile correction [64]

    const int q0 = blockIdx.x * 64;
    const int h  = blockIdx.y;
    const int b  = blockIdx.z;
    const int tid = threadIdx.x;
    const int ty = tid >> 4, tx = tid & 15;
    const size_t head_base = (size_t)(b * NH + h) * SEQ;
    const int mask_u8 = g_mask_u8;

    // Load Q tile (transposed to d-major)
    {
        int q = tid >> 2, d0 = (tid & 3) << 4;
        const float* src = g_Q + (head_base + q0 + q) * HD + d0;
#pragma unroll
        for (int j = 0; j < 16; ++j) Qt[(d0 + j) * 64 + q] = src[j];
    }
    if (tid < 64) { m_s[tid] = -INFINITY; l_s[tid] = 0.f; }

    float o[4][4];
#pragma unroll
    for (int i = 0; i < 4; ++i)
#pragma unroll
        for (int j = 0; j < 4; ++j) o[i][j] = 0.f;

    for (int k0 = 0; k0 < SEQ; k0 += 64) {
        __syncthreads();   // protect Kt/Vs/Ps reuse vs previous iteration
        {
            int r = tid >> 2, d0 = (tid & 3) << 4;
            const float* ks = g_K + (head_base + k0 + r) * HD + d0;
            const float* vs = g_V + (head_base + k0 + r) * HD + d0;
#pragma unroll
            for (int j = 0; j < 16; ++j) Kt[(d0 + j) * 64 + r] = ks[j];
#pragma unroll
            for (int j = 0; j < 16; ++j) Vs[r * 64 + d0 + j] = vs[j];
        }
        __syncthreads();

        // S = Q K^T (Q already scaled by 1/8)
        float s[4][4];
#pragma unroll
        for (int i = 0; i < 4; ++i)
#pragma unroll
            for (int j = 0; j < 4; ++j) s[i][j] = 0.f;
#pragma unroll 8
        for (int kk = 0; kk < 64; ++kk) {
            float a0 = Qt[kk * 64 + ty * 4 + 0];
            float a1 = Qt[kk * 64 + ty * 4 + 1];
            float a2 = Qt[kk * 64 + ty * 4 + 2];
            float a3 = Qt[kk * 64 + ty * 4 + 3];
            float4 bq = *(const float4*)&Kt[kk * 64 + (tx << 2)];
            s[0][0] = fmaf(a0, bq.x, s[0][0]); s[0][1] = fmaf(a0, bq.y, s[0][1]);
            s[0][2] = fmaf(a0, bq.z, s[0][2]); s[0][3] = fmaf(a0, bq.w, s[0][3]);
            s[1][0] = fmaf(a1, bq.x, s[1][0]); s[1][1] = fmaf(a1, bq.y, s[1][1]);
            s[1][2] = fmaf(a1, bq.z, s[1][2]); s[1][3] = fmaf(a1, bq.w, s[1][3]);
            s[2][0] = fmaf(a2, bq.x, s[2][0]); s[2][1] = fmaf(a2, bq.y, s[2][1]);
            s[2][2] = fmaf(a2, bq.z, s[2][2]); s[2][3] = fmaf(a2, bq.w, s[2][3]);
            s[3][0] = fmaf(a3, bq.x, s[3][0]); s[3][1] = fmaf(a3, bq.y, s[3][1]);
            s[3][2] = fmaf(a3, bq.z, s[3][2]); s[3][3] = fmaf(a3, bq.w, s[3][3]);
        }

        // Mask: where(mask) -> -10000 (replace). Element index:
        // e = (b*S + q)*S + k, 4 consecutive k per thread, e % 4 == 0.
#pragma unroll
        for (int i = 0; i < 4; ++i) {
            size_t e = ((size_t)b * SEQ + q0 + ty * 4 + i) * SEQ + k0 + (tx << 2);
            if (mask_u8) {
                unsigned mm = *(const unsigned*)(mask + e);
                if (mm & 0x000000FFu) s[i][0] = -10000.f;
                if (mm & 0x0000FF00u) s[i][1] = -10000.f;
                if (mm & 0x00FF0000u) s[i][2] = -10000.f;
                if (mm & 0xFF000000u) s[i][3] = -10000.f;
            } else {
                uint4 w = *(const uint4*)((const unsigned*)mask + e);
                if (w.x) s[i][0] = -10000.f;
                if (w.y) s[i][1] = -10000.f;
                if (w.z) s[i][2] = -10000.f;
                if (w.w) s[i][3] = -10000.f;
            }
        }

        // Row max (per-thread then cross-tx via smem)
#pragma unroll
        for (int i = 0; i < 4; ++i) {
            float rm = fmaxf(fmaxf(s[i][0], s[i][1]), fmaxf(s[i][2], s[i][3]));
            red[(ty * 4 + i) * 16 + tx] = rm;
        }
        __syncthreads();
        if (tid < 64) {
            float mt = red[tid * 16];
#pragma unroll
            for (int j = 1; j < 16; ++j) mt = fmaxf(mt, red[tid * 16 + j]);
            float mo = m_s[tid];
            float mn = fmaxf(mo, mt);
            m_s[tid] = mn;
            c_s[tid] = expf(mo - mn);   // expf(-inf)=0 on first tile
        }
        __syncthreads();

        // P = exp(S - m_new), row sums, store P to smem
#pragma unroll
        for (int i = 0; i < 4; ++i) {
            float mn = m_s[ty * 4 + i];
            float rs = 0.f;
#pragma unroll
            for (int j = 0; j < 4; ++j) {
                float p = expf(s[i][j] - mn);
                rs += p;
                Ps[(ty * 4 + i) * 64 + (tx << 2) + j] = p;
            }
            red[(ty * 4 + i) * 16 + tx] = rs;
        }
        __syncthreads();
        if (tid < 64) {
            float rs = 0.f;
#pragma unroll
            for (int j = 0; j < 16; ++j) rs += red[tid * 16 + j];
            l_s[tid] = l_s[tid] * c_s[tid] + rs;
        }

        // Rescale O, then O += P V
        float cc[4];
#pragma unroll
        for (int i = 0; i < 4; ++i) cc[i] = c_s[ty * 4 + i];
#pragma unroll
        for (int i = 0; i < 4; ++i)
#pragma unroll
            for (int j = 0; j < 4; ++j) o[i][j] *= cc[i];
#pragma unroll 8
        for (int kk = 0; kk < 64; ++kk) {
            float a0 = Ps[(ty * 4 + 0) * 64 + kk];
            float a1 = Ps[(ty * 4 + 1) * 64 + kk];
            float a2 = Ps[(ty * 4 + 2) * 64 + kk];
            float a3 = Ps[(ty * 4 + 3) * 64 + kk];
            float4 v = *(const float4*)&Vs[kk * 64 + (tx << 2)];
            o[0][0] = fmaf(a0, v.x, o[0][0]); o[0][1] = fmaf(a0, v.y, o[0][1]);
            o[0][2] = fmaf(a0, v.z, o[0][2]); o[0][3] = fmaf(a0, v.w, o[0][3]);
            o[1][0] = fmaf(a1, v.x, o[1][0]); o[1][1] = fmaf(a1, v.y, o[1][1]);
            o[1][2] = fmaf(a1, v.z, o[1][2]); o[1][3] = fmaf(a1, v.w, o[1][3]);
            o[2][0] = fmaf(a2, v.x, o[2][0]); o[2][1] = fmaf(a2, v.y, o[2][1]);
            o[2][2] = fmaf(a2, v.z, o[2][2]); o[2][3] = fmaf(a2, v.w, o[2][3]);
            o[3][0] = fmaf(a3, v.x, o[3][0]); o[3][1] = fmaf(a3, v.y, o[3][1]);
            o[3][2] = fmaf(a3, v.z, o[3][2]); o[3][3] = fmaf(a3, v.w, o[3][3]);
        }
    }
    __syncthreads();   // l_s final

    float inv[4];
#pragma unroll
    for (int i = 0; i < 4; ++i) inv[i] = 1.f / l_s[ty * 4 + i];
#pragma unroll
    for (int i = 0; i < 4; ++i) {
        float4 r = make_float4(o[i][0] * inv[i], o[i][1] * inv[i],
                               o[i][2] * inv[i], o[i][3] * inv[i]);
        *(float4*)(attn + ((size_t)b * SEQ + q0 + ty * 4 + i) * HIDD +
                   h * HD + (tx << 2)) = r;
    }
}

// ---------------------------------------------------------------------------
extern "C" void kernel_launch(void* const* d_in, const int* in_sizes, int n_in,
                              void* d_out, int out_size) {
    (void)in_sizes; (void)n_in; (void)out_size;
    const float* hidden        = (const float*)d_in[0];
    const unsigned char* mask  = (const unsigned char*)d_in[1];
    const int* pos             = (const int*)d_in[2];
    const float* Wqkv          = (const float*)d_in[3];
    const float* Wo            = (const float*)d_in[4];
    float* out                 = (float*)d_out;

    float* qkv = nullptr;
    float* attn = nullptr;
    cudaGetSymbolAddress((void**)&qkv, g_qkv);
    cudaGetSymbolAddress((void**)&attn, g_attn);

    const int smem_bytes = (4 * 64 * 64 + 64 * 16 + 3 * 64) * (int)sizeof(float); // 70400
    cudaFuncSetAttribute(flash_attn, cudaFuncAttributeMaxDynamicSharedMemorySize,
                         smem_bytes);

    detect_mask_kernel<<<1, 256>>>(mask);

    dim3 gqkv(NQKV / 128, MROWS / 128);        // 48 x 32
    sgemm_nt<<<gqkv, 256>>>(hidden, Wqkv, qkv, HIDD, NQKV);

    rope_scatter<<<(NB * SEQ * NH * 32) / 256, 256>>>(qkv, pos);

    dim3 gatt(SEQ / 64, NH, NB);               // 32 x 32 x 2
    flash_attn<<<gatt, 256, smem_bytes>>>(mask, attn);

    dim3 go(HIDD / 128, MROWS / 128);          // 16 x 32
    sgemm_nt<<<go, 256>>>(attn, Wo, out, HIDD, HIDD);
}

// round 12
// speedup vs baseline: 1.2754x; 1.2754x over previous
#include <cuda_runtime.h>
#include <cuda_bf16.h>
#include <math.h>
#include <stdint.h>

#define SEQ   2048
#define NH    32
#define HD    64
#define HIDD  2048
#define NB    2
#define NQKV  (3 * NH * HD)   // 6144
#define MROWS (NB * SEQ)      // 4096

// ---------------------------------------------------------------------------
// Scratch (__device__ globals per harness rules — no cudaMalloc anywhere)
// ---------------------------------------------------------------------------
__device__ float g_qkv[(size_t)MROWS * NQKV];          // [4096][6144] raw QKV fp32
__device__ float g_Q[(size_t)NB * NH * SEQ * HD];      // [B,H,S,D], pre-scaled by 1/8
__device__ float g_K[(size_t)NB * NH * SEQ * HD];
__device__ float g_V[(size_t)NB * NH * SEQ * HD];
__device__ float g_attn[(size_t)MROWS * HIDD];         // [4096][2048]
__device__ int   g_mask_u8;                            // 1 = 1-byte bool, 0 = 4-byte words
// bf16x3 decomposition buffers (reused: hidden->x then attn->x; Wqkv->w then Wo->w)
__device__ __nv_bfloat16 g_xhi[(size_t)MROWS * HIDD];
__device__ __nv_bfloat16 g_xlo[(size_t)MROWS * HIDD];
__device__ __nv_bfloat16 g_whi[(size_t)NQKV * HIDD];
__device__ __nv_bfloat16 g_wlo[(size_t)NQKV * HIDD];

// ---------------------------------------------------------------------------
// Warp-MMA helpers (portable PTX: sm_80+, no 'a'-feature instructions)
// ---------------------------------------------------------------------------
__device__ __forceinline__ uint32_t smem_u32(const void* p) {
    uint32_t a;
    asm("{ .reg .u64 t; cvta.to.shared.u64 t, %1; cvt.u32.u64 %0, t; }"
        : "=r"(a) : "l"(p));
    return a;
}

__device__ __forceinline__ void ldsm4(uint32_t addr, uint32_t* r) {
    asm volatile("ldmatrix.sync.aligned.m8n8.x4.shared.b16 {%0,%1,%2,%3}, [%4];"
                 : "=r"(r[0]), "=r"(r[1]), "=r"(r[2]), "=r"(r[3]) : "r"(addr));
}

__device__ __forceinline__ void mma16816(float* c, const uint32_t* a,
                                         uint32_t b0, uint32_t b1) {
    asm volatile(
        "mma.sync.aligned.m16n8k16.row.col.f32.bf16.bf16.f32 "
        "{%0,%1,%2,%3}, {%4,%5,%6,%7}, {%8,%9}, {%0,%1,%2,%3};"
        : "+f"(c[0]), "+f"(c[1]), "+f"(c[2]), "+f"(c[3])
        : "r"(a[0]), "r"(a[1]), "r"(a[2]), "r"(a[3]), "r"(b0), "r"(b1));
}

// ---------------------------------------------------------------------------
// Decompose fp32 -> bf16 hi + bf16 lo (x ~= hi + lo, residual ~2^-17 x)
// ---------------------------------------------------------------------------
__global__ __launch_bounds__(256) void decompose_kernel(
        const float4* __restrict__ x, __nv_bfloat162* __restrict__ hi,
        __nv_bfloat162* __restrict__ lo, int n4) {
    int i = blockIdx.x * blockDim.x + threadIdx.x;
    if (i >= n4) return;
    float4 v = x[i];
    __nv_bfloat16 h0 = __float2bfloat16(v.x), h1 = __float2bfloat16(v.y);
    __nv_bfloat16 h2 = __float2bfloat16(v.z), h3 = __float2bfloat16(v.w);
    __nv_bfloat16 l0 = __float2bfloat16(v.x - __bfloat162float(h0));
    __nv_bfloat16 l1 = __float2bfloat16(v.y - __bfloat162float(h1));
    __nv_bfloat16 l2 = __float2bfloat16(v.z - __bfloat162float(h2));
    __nv_bfloat16 l3 = __float2bfloat16(v.w - __bfloat162float(h3));
    hi[2 * i]     = __halves2bfloat162(h0, h1);
    hi[2 * i + 1] = __halves2bfloat162(h2, h3);
    lo[2 * i]     = __halves2bfloat162(l0, l1);
    lo[2 * i + 1] = __halves2bfloat162(l2, l3);
}

// ---------------------------------------------------------------------------
// C[m][n] = sum_k A[m][k]*B[n][k] via bf16x3 HMMA (AhBh + AlBh + AhBl).
// 128x128 CTA tile, BK=32, 8 warps in a 2(m) x 4(n) grid, each 64x32
// (4x4 grid of m16n8k16). fp32 accumulators in registers.
// SMEM: 4 tiles 128 x 32 bf16 padded to stride 40 (80 B/row) = 40960 B.
// ---------------------------------------------------------------------------
#define SSTR 40

__global__ __launch_bounds__(256) void hmma_gemm(
        const __nv_bfloat16* __restrict__ Ah, const __nv_bfloat16* __restrict__ Al,
        const __nv_bfloat16* __restrict__ Bh, const __nv_bfloat16* __restrict__ Bl,
        float* __restrict__ C, int K, int N) {
    __shared__ __align__(16) __nv_bfloat16 sAh[128 * SSTR];
    __shared__ __align__(16) __nv_bfloat16 sAl[128 * SSTR];
    __shared__ __align__(16) __nv_bfloat16 sBh[128 * SSTR];
    __shared__ __align__(16) __nv_bfloat16 sBl[128 * SSTR];

    const int tid = threadIdx.x;
    const int wid = tid >> 5;
    const int lane = tid & 31;
    const int warp_m = wid & 1;        // 0..1 (64 rows each)
    const int warp_n = wid >> 1;       // 0..3 (32 cols each)
    const int m0 = blockIdx.y * 128, n0 = blockIdx.x * 128;

    // gmem load mapping: 2 threads per row, 32 B (2 x uint4) each
    const int lr = tid >> 1;           // 0..127
    const int ls = (tid & 1) << 4;     // 0 or 16 (bf16 elems)
    const __nv_bfloat16* pAh = Ah + (size_t)(m0 + lr) * K + ls;
    const __nv_bfloat16* pAl = Al + (size_t)(m0 + lr) * K + ls;
    const __nv_bfloat16* pBh = Bh + (size_t)(n0 + lr) * K + ls;
    const __nv_bfloat16* pBl = Bl + (size_t)(n0 + lr) * K + ls;
    const int so = lr * SSTR + ls;

    // ldmatrix address components
    const int a_row = lane & 15;                 // row within 16
    const int a_col = (lane >> 4) << 3;          // 0 or 8 (k)
    const int b_n   = (lane & 7) + ((lane & 16) ? 8 : 0);
    const int b_k   = (lane & 8) ? 8 : 0;
    const uint32_t uAh = smem_u32(sAh), uAl = smem_u32(sAl);
    const uint32_t uBh = smem_u32(sBh), uBl = smem_u32(sBl);

    float acc[4][4][4];
#pragma unroll
    for (int i = 0; i < 4; ++i)
#pragma unroll
        for (int j = 0; j < 4; ++j)
#pragma unroll
            for (int v = 0; v < 4; ++v) acc[i][j][v] = 0.f;

    const int kIters = K >> 5;
    for (int it = 0; it < kIters; ++it) {
        const int k0 = it << 5;
        uint4 vah0 = *(const uint4*)(pAh + k0), vah1 = *(const uint4*)(pAh + k0 + 8);
        uint4 val0 = *(const uint4*)(pAl + k0), val1 = *(const uint4*)(pAl + k0 + 8);
        uint4 vbh0 = *(const uint4*)(pBh + k0), vbh1 = *(const uint4*)(pBh + k0 + 8);
        uint4 vbl0 = *(const uint4*)(pBl + k0), vbl1 = *(const uint4*)(pBl + k0 + 8);
        __syncthreads();   // previous iteration's reads done
        *(uint4*)(sAh + so) = vah0; *(uint4*)(sAh + so + 8) = vah1;
        *(uint4*)(sAl + so) = val0; *(uint4*)(sAl + so + 8) = val1;
        *(uint4*)(sBh + so) = vbh0; *(uint4*)(sBh + so + 8) = vbh1;
        *(uint4*)(sBl + so) = vbl0; *(uint4*)(sBl + so + 8) = vbl1;
        __syncthreads();

#pragma unroll
        for (int ks = 0; ks < 2; ++ks) {
            const int kb = ks << 4;
            uint32_t bh[2][4], bl[2][4];
#pragma unroll
            for (int np = 0; np < 2; ++np) {
                uint32_t boff = (uint32_t)(((warp_n * 32 + np * 16 + b_n) * SSTR
                                            + kb + b_k) * 2);
                ldsm4(uBh + boff, bh[np]);
                ldsm4(uBl + boff, bl[np]);
            }
#pragma unroll
            for (int mt = 0; mt < 4; ++mt) {
                uint32_t aoff = (uint32_t)(((warp_m * 64 + mt * 16 + a_row) * SSTR
                                            + kb + a_col) * 2);
                uint32_t ahf[4], alf[4];
                ldsm4(uAh + aoff, ahf);
                ldsm4(uAl + aoff, alf);
#pragma unroll
                for (int nt = 0; nt < 4; ++nt) {
                    uint32_t b0h = bh[nt >> 1][(nt & 1) * 2];
                    uint32_t b1h = bh[nt >> 1][(nt & 1) * 2 + 1];
                    uint32_t b0l = bl[nt >> 1][(nt & 1) * 2];
                    uint32_t b1l = bl[nt >> 1][(nt & 1) * 2 + 1];
                    mma16816(acc[mt][nt], ahf, b0h, b1h);
                    mma16816(acc[mt][nt], alf, b0h, b1h);
                    mma16816(acc[mt][nt], ahf, b0l, b1l);
                }
            }
        }
    }

    // Epilogue: fragment layout -> C
#pragma unroll
    for (int mt = 0; mt < 4; ++mt) {
#pragma unroll
        for (int nt = 0; nt < 4; ++nt) {
            int r = m0 + warp_m * 64 + mt * 16 + (lane >> 2);
            int c = n0 + warp_n * 32 + nt * 8 + (lane & 3) * 2;
            float2 lo = make_float2(acc[mt][nt][0], acc[mt][nt][1]);
            float2 hi = make_float2(acc[mt][nt][2], acc[mt][nt][3]);
            *(float2*)(C + (size_t)r * N + c) = lo;
            *(float2*)(C + (size_t)(r + 8) * N + c) = hi;
        }
    }
}

// ---------------------------------------------------------------------------
// Detect the attention_mask element width (1-byte bool vs 4-byte words).
// ---------------------------------------------------------------------------
__global__ void detect_mask_kernel(const unsigned char* __restrict__ m) {
    __shared__ int found;
    if (threadIdx.x == 0) found = 0;
    __syncthreads();
    const uint4* p = (const uint4*)m;
    int f = 0;
    for (int i = threadIdx.x; i < 65536; i += blockDim.x) {
        uint4 w = p[i];
        unsigned ws[4] = {w.x, w.y, w.z, w.w};
#pragma unroll
        for (int j = 0; j < 4; ++j) {
            unsigned v = ws[j];
            if (((v >> 8) & 0xFFu) == 1u || ((v >> 16) & 0xFFu) == 1u ||
                ((v >> 24) & 0xFFu) == 1u)
                f = 1;
        }
    }
    if (f) atomicOr(&found, 1);
    __syncthreads();
    if (threadIdx.x == 0) g_mask_u8 = found;
}

// ---------------------------------------------------------------------------
// Split raw QKV into Q/K/V [B,H,S,D]; apply RoPE; fold 1/sqrt(D) into Q.
// ---------------------------------------------------------------------------
__global__ __launch_bounds__(256) void rope_scatter(const float* __restrict__ qkv,
                                                    const int* __restrict__ pos_ids) {
    int idx = blockIdx.x * blockDim.x + threadIdx.x;
    int d = idx & 31;
    int h = (idx >> 5) & (NH - 1);
    int s = (idx >> 10) & (SEQ - 1);
    int b = idx >> 21;
    int pos = pos_ids[b * SEQ + s];

    const float* src = qkv + (size_t)(b * SEQ + s) * NQKV + h * (3 * HD);
    float q1 = src[d],       q2 = src[d + 32];
    float k1 = src[64 + d],  k2 = src[96 + d];
    float v1 = src[128 + d], v2 = src[160 + d];

    float invf = (float)pow(10000.0, -(double)d / 32.0);
    float t = (float)pos * invf;
    float sn = (float)sin((double)t);
    float cs = (float)cos((double)t);

    size_t dst = ((size_t)(b * NH + h) * SEQ + s) * HD;
    const float qs = 0.125f;
    g_Q[dst + d]      = (q1 * cs - q2 * sn) * qs;
    g_Q[dst + d + 32] = (q2 * cs + q1 * sn) * qs;
    g_K[dst + d]      = k1 * cs - k2 * sn;
    g_K[dst + d + 32] = k2 * cs + k1 * sn;
    g_V[dst + d]      = v1;
    g_V[dst + d + 32] = v2;
}

// ---------------------------------------------------------------------------
// Flash attention, fp32. One block per (b, h, 64-row q tile). 256 threads.
// ---------------------------------------------------------------------------
__global__ __launch_bounds__(256) void flash_attn(const unsigned char* __restrict__ mask,
                                                  float* __restrict__ attn) {
    extern __shared__ float sm[];
    float* Qt  = sm;               // [64 d][64 q]
    float* Kt  = Qt + 64 * 64;     // [64 d][64 k]
    float* Vs  = Kt + 64 * 64;     // [64 k][64 d]
    float* Ps  = Vs + 64 * 64;     // [64 q][64 k]
    float* red = Ps + 64 * 64;     // [64 q][16 tx]
    float* m_s = red + 64 * 16;
    float* l_s = m_s + 64;
    float* c_s = l_s + 64;

    const int q0 = blockIdx.x * 64;
    const int h  = blockIdx.y;
    const int b  = blockIdx.z;
    const int tid = threadIdx.x;
    const int ty = tid >> 4, tx = tid & 15;
    const size_t head_base = (size_t)(b * NH + h) * SEQ;
    const int mask_u8 = g_mask_u8;

    {
        int q = tid >> 2, d0 = (tid & 3) << 4;
        const float* src = g_Q + (head_base + q0 + q) * HD + d0;
#pragma unroll
        for (int j = 0; j < 16; ++j) Qt[(d0 + j) * 64 + q] = src[j];
    }
    if (tid < 64) { m_s[tid] = -INFINITY; l_s[tid] = 0.f; }

    float o[4][4];
#pragma unroll
    for (int i = 0; i < 4; ++i)
#pragma unroll
        for (int j = 0; j < 4; ++j) o[i][j] = 0.f;

    for (int k0 = 0; k0 < SEQ; k0 += 64) {
        __syncthreads();
        {
            int r = tid >> 2, d0 = (tid & 3) << 4;
            const float* ks = g_K + (head_base + k0 + r) * HD + d0;
            const float* vs = g_V + (head_base + k0 + r) * HD + d0;
#pragma unroll
            for (int j = 0; j < 16; ++j) Kt[(d0 + j) * 64 + r] = ks[j];
#pragma unroll
            for (int j = 0; j < 16; ++j) Vs[r * 64 + d0 + j] = vs[j];
        }
        __syncthreads();

        float s[4][4];
#pragma unroll
        for (int i = 0; i < 4; ++i)
#pragma unroll
            for (int j = 0; j < 4; ++j) s[i][j] = 0.f;
#pragma unroll 8
        for (int kk = 0; kk < 64; ++kk) {
            float a0 = Qt[kk * 64 + ty * 4 + 0];
            float a1 = Qt[kk * 64 + ty * 4 + 1];
            float a2 = Qt[kk * 64 + ty * 4 + 2];
            float a3 = Qt[kk * 64 + ty * 4 + 3];
            float4 bq = *(const float4*)&Kt[kk * 64 + (tx << 2)];
            s[0][0] = fmaf(a0, bq.x, s[0][0]); s[0][1] = fmaf(a0, bq.y, s[0][1]);
            s[0][2] = fmaf(a0, bq.z, s[0][2]); s[0][3] = fmaf(a0, bq.w, s[0][3]);
            s[1][0] = fmaf(a1, bq.x, s[1][0]); s[1][1] = fmaf(a1, bq.y, s[1][1]);
            s[1][2] = fmaf(a1, bq.z, s[1][2]); s[1][3] = fmaf(a1, bq.w, s[1][3]);
            s[2][0] = fmaf(a2, bq.x, s[2][0]); s[2][1] = fmaf(a2, bq.y, s[2][1]);
            s[2][2] = fmaf(a2, bq.z, s[2][2]); s[2][3] = fmaf(a2, bq.w, s[2][3]);
            s[3][0] = fmaf(a3, bq.x, s[3][0]); s[3][1] = fmaf(a3, bq.y, s[3][1]);
            s[3][2] = fmaf(a3, bq.z, s[3][2]); s[3][3] = fmaf(a3, bq.w, s[3][3]);
        }

#pragma unroll
        for (int i = 0; i < 4; ++i) {
            size_t e = ((size_t)b * SEQ + q0 + ty * 4 + i) * SEQ + k0 + (tx << 2);
            if (mask_u8) {
                unsigned mm = *(const unsigned*)(mask + e);
                if (mm & 0x000000FFu) s[i][0] = -10000.f;
                if (mm & 0x0000FF00u) s[i][1] = -10000.f;
                if (mm & 0x00FF0000u) s[i][2] = -10000.f;
                if (mm & 0xFF000000u) s[i][3] = -10000.f;
            } else {
                uint4 w = *(const uint4*)((const unsigned*)mask + e);
                if (w.x) s[i][0] = -10000.f;
                if (w.y) s[i][1] = -10000.f;
                if (w.z) s[i][2] = -10000.f;
                if (w.w) s[i][3] = -10000.f;
            }
        }

#pragma unroll
        for (int i = 0; i < 4; ++i) {
            float rm = fmaxf(fmaxf(s[i][0], s[i][1]), fmaxf(s[i][2], s[i][3]));
            red[(ty * 4 + i) * 16 + tx] = rm;
        }
        __syncthreads();
        if (tid < 64) {
            float mt = red[tid * 16];
#pragma unroll
            for (int j = 1; j < 16; ++j) mt = fmaxf(mt, red[tid * 16 + j]);
            float mo = m_s[tid];
            float mn = fmaxf(mo, mt);
            m_s[tid] = mn;
            c_s[tid] = __expf(mo - mn);
        }
        __syncthreads();

#pragma unroll
        for (int i = 0; i < 4; ++i) {
            float mn = m_s[ty * 4 + i];
            float rs = 0.f;
#pragma unroll
            for (int j = 0; j < 4; ++j) {
                float p = __expf(s[i][j] - mn);
                rs += p;
                Ps[(ty * 4 + i) * 64 + (tx << 2) + j] = p;
            }
            red[(ty * 4 + i) * 16 + tx] = rs;
        }
        __syncthreads();
        if (tid < 64) {
            float rs = 0.f;
#pragma unroll
            for (int j = 0; j < 16; ++j) rs += red[tid * 16 + j];
            l_s[tid] = l_s[tid] * c_s[tid] + rs;
        }

        float cc[4];
#pragma unroll
        for (int i = 0; i < 4; ++i) cc[i] = c_s[ty * 4 + i];
#pragma unroll
        for (int i = 0; i < 4; ++i)
#pragma unroll
            for (int j = 0; j < 4; ++j) o[i][j] *= cc[i];
#pragma unroll 8
        for (int kk = 0; kk < 64; ++kk) {
            float a0 = Ps[(ty * 4 + 0) * 64 + kk];
            float a1 = Ps[(ty * 4 + 1) * 64 + kk];
            float a2 = Ps[(ty * 4 + 2) * 64 + kk];
            float a3 = Ps[(ty * 4 + 3) * 64 + kk];
            float4 v = *(const float4*)&Vs[kk * 64 + (tx << 2)];
            o[0][0] = fmaf(a0, v.x, o[0][0]); o[0][1] = fmaf(a0, v.y, o[0][1]);
            o[0][2] = fmaf(a0, v.z, o[0][2]); o[0][3] = fmaf(a0, v.w, o[0][3]);
            o[1][0] = fmaf(a1, v.x, o[1][0]); o[1][1] = fmaf(a1, v.y, o[1][1]);
            o[1][2] = fmaf(a1, v.z, o[1][2]); o[1][3] = fmaf(a1, v.w, o[1][3]);
            o[2][0] = fmaf(a2, v.x, o[2][0]); o[2][1] = fmaf(a2, v.y, o[2][1]);
            o[2][2] = fmaf(a2, v.z, o[2][2]); o[2][3] = fmaf(a2, v.w, o[2][3]);
            o[3][0] = fmaf(a3, v.x, o[3][0]); o[3][1] = fmaf(a3, v.y, o[3][1]);
            o[3][2] = fmaf(a3, v.z, o[3][2]); o[3][3] = fmaf(a3, v.w, o[3][3]);
        }
    }
    __syncthreads();

    float inv[4];
#pragma unroll
    for (int i = 0; i < 4; ++i) inv[i] = 1.f / l_s[ty * 4 + i];
#pragma unroll
    for (int i = 0; i < 4; ++i) {
        float4 r = make_float4(o[i][0] * inv[i], o[i][1] * inv[i],
                               o[i][2] * inv[i], o[i][3] * inv[i]);
        *(float4*)(attn + ((size_t)b * SEQ + q0 + ty * 4 + i) * HIDD +
                   h * HD + (tx << 2)) = r;
    }
}

// ---------------------------------------------------------------------------
extern "C" void kernel_launch(void* const* d_in, const int* in_sizes, int n_in,
                              void* d_out, int out_size) {
    (void)in_sizes; (void)n_in; (void)out_size;
    const float* hidden        = (const float*)d_in[0];
    const unsigned char* mask  = (const unsigned char*)d_in[1];
    const int* pos             = (const int*)d_in[2];
    const float* Wqkv          = (const float*)d_in[3];
    const float* Wo            = (const float*)d_in[4];
    float* out                 = (float*)d_out;

    float *qkv = nullptr, *attn = nullptr;
    __nv_bfloat16 *xhi, *xlo, *whi, *wlo;
    cudaGetSymbolAddress((void**)&qkv, g_qkv);
    cudaGetSymbolAddress((void**)&attn, g_attn);
    cudaGetSymbolAddress((void**)&xhi, g_xhi);
    cudaGetSymbolAddress((void**)&xlo, g_xlo);
    cudaGetSymbolAddress((void**)&whi, g_whi);
    cudaGetSymbolAddress((void**)&wlo, g_wlo);

    const int flash_smem = (4 * 64 * 64 + 64 * 16 + 3 * 64) * (int)sizeof(float);
    cudaFuncSetAttribute(flash_attn, cudaFuncAttributeMaxDynamicSharedMemorySize,
                         flash_smem);

    detect_mask_kernel<<<1, 256>>>(mask);

    // QKV projection: decompose, bf16x3 HMMA GEMM
    decompose_kernel<<<(MROWS * HIDD / 4) / 256, 256>>>(
        (const float4*)hidden, (__nv_bfloat162*)xhi, (__nv_bfloat162*)xlo,
        MROWS * HIDD / 4);
    decompose_kernel<<<(NQKV * HIDD / 4) / 256, 256>>>(
        (const float4*)Wqkv, (__nv_bfloat162*)whi, (__nv_bfloat162*)wlo,
        NQKV * HIDD / 4);
    hmma_gemm<<<dim3(NQKV / 128, MROWS / 128), 256>>>(
        xhi, xlo, whi, wlo, qkv, HIDD, NQKV);

    rope_scatter<<<(NB * SEQ * NH * 32) / 256, 256>>>(qkv, pos);

    dim3 gatt(SEQ / 64, NH, NB);
    flash_attn<<<gatt, 256, flash_smem>>>(mask, attn);

    // O projection
    decompose_kernel<<<(MROWS * HIDD / 4) / 256, 256>>>(
        (const float4*)attn, (__nv_bfloat162*)xhi, (__nv_bfloat162*)xlo,
        MROWS * HIDD / 4);
    decompose_kernel<<<(HIDD * HIDD / 4) / 256, 256>>>(
        (const float4*)Wo, (__nv_bfloat162*)whi, (__nv_bfloat162*)wlo,
        HIDD * HIDD / 4);
    hmma_gemm<<<dim3(HIDD / 128, MROWS / 128), 256>>>(
        xhi, xlo, whi, wlo, out, HIDD, HIDD);
}

// round 13
// speedup vs baseline: 1.8735x; 1.4690x over previous
#include <cuda_runtime.h>
#include <cuda_bf16.h>
#include <math.h>
#include <stdint.h>

#define SEQ   2048
#define NH    32
#define HD    64
#define HIDD  2048
#define NB    2
#define NQKV  (3 * NH * HD)   // 6144
#define MROWS (NB * SEQ)      // 4096

// ---------------------------------------------------------------------------
// Scratch (__device__ globals per harness rules — no cudaMalloc anywhere)
// ---------------------------------------------------------------------------
__device__ float g_qkv[(size_t)MROWS * NQKV];
__device__ float g_attn[(size_t)MROWS * HIDD];
__device__ int   g_mask_u8;
// GEMM decomposition buffers
__device__ __nv_bfloat16 g_xhi[(size_t)MROWS * HIDD];
__device__ __nv_bfloat16 g_xlo[(size_t)MROWS * HIDD];
__device__ __nv_bfloat16 g_whi[(size_t)NQKV * HIDD];
__device__ __nv_bfloat16 g_wlo[(size_t)NQKV * HIDD];
// Attention operands, bf16 hi/lo
__device__ __nv_bfloat16 g_Qhi[(size_t)NB * NH * SEQ * HD];  // [B,H,S,D], scaled 1/8
__device__ __nv_bfloat16 g_Qlo[(size_t)NB * NH * SEQ * HD];
__device__ __nv_bfloat16 g_Khi[(size_t)NB * NH * SEQ * HD];  // [B,H,S,D]
__device__ __nv_bfloat16 g_Klo[(size_t)NB * NH * SEQ * HD];
__device__ __nv_bfloat16 g_Vthi[(size_t)NB * NH * HD * SEQ]; // [B,H,D,S] transposed
__device__ __nv_bfloat16 g_Vtlo[(size_t)NB * NH * HD * SEQ];

// ---------------------------------------------------------------------------
// Warp-MMA helpers (portable PTX: sm_80+)
// ---------------------------------------------------------------------------
__device__ __forceinline__ uint32_t smem_u32(const void* p) {
    uint32_t a;
    asm("{ .reg .u64 t; cvta.to.shared.u64 t, %1; cvt.u32.u64 %0, t; }"
        : "=r"(a) : "l"(p));
    return a;
}

__device__ __forceinline__ void ldsm4(uint32_t addr, uint32_t* r) {
    asm volatile("ldmatrix.sync.aligned.m8n8.x4.shared.b16 {%0,%1,%2,%3}, [%4];"
                 : "=r"(r[0]), "=r"(r[1]), "=r"(r[2]), "=r"(r[3]) : "r"(addr));
}

__device__ __forceinline__ void mma16816(float* c, const uint32_t* a,
                                         uint32_t b0, uint32_t b1) {
    asm volatile(
        "mma.sync.aligned.m16n8k16.row.col.f32.bf16.bf16.f32 "
        "{%0,%1,%2,%3}, {%4,%5,%6,%7}, {%8,%9}, {%0,%1,%2,%3};"
        : "+f"(c[0]), "+f"(c[1]), "+f"(c[2]), "+f"(c[3])
        : "r"(a[0]), "r"(a[1]), "r"(a[2]), "r"(a[3]), "r"(b0), "r"(b1));
}

// Fast exp on the FMA pipe (avoids MUFU bottleneck). x <= 0; ~1e-7 rel.
__device__ __forceinline__ float fexp(float x) {
    x = fmaxf(x, -80.f);
    float t = fmaf(x, 1.4426950408889634f, 12582912.f);
    float n = t - 12582912.f;
    float f = fmaf(x, 1.4426950408889634f, -n);
    float p = 1.8775767e-3f;
    p = fmaf(p, f, 8.9893397e-3f);
    p = fmaf(p, f, 5.5826318e-2f);
    p = fmaf(p, f, 2.4015361e-1f);
    p = fmaf(p, f, 6.9315308e-1f);
    p = fmaf(p, f, 1.0f);
    return __int_as_float(__float_as_int(p) + (__float_as_int(t) << 23));
}

// float pair -> bf16x2 hi reg + bf16x2 lo reg
__device__ __forceinline__ void pack3(float f0, float f1, uint32_t& rh, uint32_t& rl) {
    __nv_bfloat16 h0 = __float2bfloat16(f0), h1 = __float2bfloat16(f1);
    __nv_bfloat16 l0 = __float2bfloat16(f0 - __bfloat162float(h0));
    __nv_bfloat16 l1 = __float2bfloat16(f1 - __bfloat162float(h1));
    __nv_bfloat162 H = __halves2bfloat162(h0, h1);
    __nv_bfloat162 L = __halves2bfloat162(l0, l1);
    rh = *(uint32_t*)&H;
    rl = *(uint32_t*)&L;
}

// ---------------------------------------------------------------------------
// Decompose fp32 -> bf16 hi + lo
// ---------------------------------------------------------------------------
__global__ __launch_bounds__(256) void decompose_kernel(
        const float4* __restrict__ x, __nv_bfloat162* __restrict__ hi,
        __nv_bfloat162* __restrict__ lo, int n4) {
    int i = blockIdx.x * blockDim.x + threadIdx.x;
    if (i >= n4) return;
    float4 v = x[i];
    __nv_bfloat16 h0 = __float2bfloat16(v.x), h1 = __float2bfloat16(v.y);
    __nv_bfloat16 h2 = __float2bfloat16(v.z), h3 = __float2bfloat16(v.w);
    __nv_bfloat16 l0 = __float2bfloat16(v.x - __bfloat162float(h0));
    __nv_bfloat16 l1 = __float2bfloat16(v.y - __bfloat162float(h1));
    __nv_bfloat16 l2 = __float2bfloat16(v.z - __bfloat162float(h2));
    __nv_bfloat16 l3 = __float2bfloat16(v.w - __bfloat162float(h3));
    hi[2 * i]     = __halves2bfloat162(h0, h1);
    hi[2 * i + 1] = __halves2bfloat162(h2, h3);
    lo[2 * i]     = __halves2bfloat162(l0, l1);
    lo[2 * i + 1] = __halves2bfloat162(l2, l3);
}

// ---------------------------------------------------------------------------
// Projection GEMM: C[m][n] = sum_k A[m][k]*B[n][k], bf16x3 HMMA (unchanged R12)
// ---------------------------------------------------------------------------
#define SSTR 40

__global__ __launch_bounds__(256) void hmma_gemm(
        const __nv_bfloat16* __restrict__ Ah, const __nv_bfloat16* __restrict__ Al,
        const __nv_bfloat16* __restrict__ Bh, const __nv_bfloat16* __restrict__ Bl,
        float* __restrict__ C, int K, int N) {
    __shared__ __align__(16) __nv_bfloat16 sAh[128 * SSTR];
    __shared__ __align__(16) __nv_bfloat16 sAl[128 * SSTR];
    __shared__ __align__(16) __nv_bfloat16 sBh[128 * SSTR];
    __shared__ __align__(16) __nv_bfloat16 sBl[128 * SSTR];

    const int tid = threadIdx.x;
    const int wid = tid >> 5;
    const int lane = tid & 31;
    const int warp_m = wid & 1;
    const int warp_n = wid >> 1;
    const int m0 = blockIdx.y * 128, n0 = blockIdx.x * 128;

    const int lr = tid >> 1;
    const int ls = (tid & 1) << 4;
    const __nv_bfloat16* pAh = Ah + (size_t)(m0 + lr) * K + ls;
    const __nv_bfloat16* pAl = Al + (size_t)(m0 + lr) * K + ls;
    const __nv_bfloat16* pBh = Bh + (size_t)(n0 + lr) * K + ls;
    const __nv_bfloat16* pBl = Bl + (size_t)(n0 + lr) * K + ls;
    const int so = lr * SSTR + ls;

    const int a_row = lane & 15;
    const int a_col = (lane >> 4) << 3;
    const int b_n   = (lane & 7) + ((lane & 16) ? 8 : 0);
    const int b_k   = (lane & 8) ? 8 : 0;
    const uint32_t uAh = smem_u32(sAh), uAl = smem_u32(sAl);
    const uint32_t uBh = smem_u32(sBh), uBl = smem_u32(sBl);

    float acc[4][4][4];
#pragma unroll
    for (int i = 0; i < 4; ++i)
#pragma unroll
        for (int j = 0; j < 4; ++j)
#pragma unroll
            for (int v = 0; v < 4; ++v) acc[i][j][v] = 0.f;

    const int kIters = K >> 5;
    for (int it = 0; it < kIters; ++it) {
        const int k0 = it << 5;
        uint4 vah0 = *(const uint4*)(pAh + k0), vah1 = *(const uint4*)(pAh + k0 + 8);
        uint4 val0 = *(const uint4*)(pAl + k0), val1 = *(const uint4*)(pAl + k0 + 8);
        uint4 vbh0 = *(const uint4*)(pBh + k0), vbh1 = *(const uint4*)(pBh + k0 + 8);
        uint4 vbl0 = *(const uint4*)(pBl + k0), vbl1 = *(const uint4*)(pBl + k0 + 8);
        __syncthreads();
        *(uint4*)(sAh + so) = vah0; *(uint4*)(sAh + so + 8) = vah1;
        *(uint4*)(sAl + so) = val0; *(uint4*)(sAl + so + 8) = val1;
        *(uint4*)(sBh + so) = vbh0; *(uint4*)(sBh + so + 8) = vbh1;
        *(uint4*)(sBl + so) = vbl0; *(uint4*)(sBl + so + 8) = vbl1;
        __syncthreads();

#pragma unroll
        for (int ks = 0; ks < 2; ++ks) {
            const int kb = ks << 4;
            uint32_t bh[2][4], bl[2][4];
#pragma unroll
            for (int np = 0; np < 2; ++np) {
                uint32_t boff = (uint32_t)(((warp_n * 32 + np * 16 + b_n) * SSTR
                                            + kb + b_k) * 2);
                ldsm4(uBh + boff, bh[np]);
                ldsm4(uBl + boff, bl[np]);
            }
#pragma unroll
            for (int mt = 0; mt < 4; ++mt) {
                uint32_t aoff = (uint32_t)(((warp_m * 64 + mt * 16 + a_row) * SSTR
                                            + kb + a_col) * 2);
                uint32_t ahf[4], alf[4];
                ldsm4(uAh + aoff, ahf);
                ldsm4(uAl + aoff, alf);
#pragma unroll
                for (int nt = 0; nt < 4; ++nt) {
                    uint32_t b0h = bh[nt >> 1][(nt & 1) * 2];
                    uint32_t b1h = bh[nt >> 1][(nt & 1) * 2 + 1];
                    uint32_t b0l = bl[nt >> 1][(nt & 1) * 2];
                    uint32_t b1l = bl[nt >> 1][(nt & 1) * 2 + 1];
                    mma16816(acc[mt][nt], ahf, b0h, b1h);
                    mma16816(acc[mt][nt], alf, b0h, b1h);
                    mma16816(acc[mt][nt], ahf, b0l, b1l);
                }
            }
        }
    }

#pragma unroll
    for (int mt = 0; mt < 4; ++mt) {
#pragma unroll
        for (int nt = 0; nt < 4; ++nt) {
            int r = m0 + warp_m * 64 + mt * 16 + (lane >> 2);
            int c = n0 + warp_n * 32 + nt * 8 + (lane & 3) * 2;
            float2 lo = make_float2(acc[mt][nt][0], acc[mt][nt][1]);
            float2 hi = make_float2(acc[mt][nt][2], acc[mt][nt][3]);
            *(float2*)(C + (size_t)r * N + c) = lo;
            *(float2*)(C + (size_t)(r + 8) * N + c) = hi;
        }
    }
}

// ---------------------------------------------------------------------------
// Mask element-width detection (1-byte bool vs 4-byte words)
// ---------------------------------------------------------------------------
__global__ void detect_mask_kernel(const unsigned char* __restrict__ m) {
    __shared__ int found;
    if (threadIdx.x == 0) found = 0;
    __syncthreads();
    const uint4* p = (const uint4*)m;
    int f = 0;
    for (int i = threadIdx.x; i < 65536; i += blockDim.x) {
        uint4 w = p[i];
        unsigned ws[4] = {w.x, w.y, w.z, w.w};
#pragma unroll
        for (int j = 0; j < 4; ++j) {
            unsigned v = ws[j];
            if (((v >> 8) & 0xFFu) == 1u || ((v >> 16) & 0xFFu) == 1u ||
                ((v >> 24) & 0xFFu) == 1u)
                f = 1;
        }
    }
    if (f) atomicOr(&found, 1);
    __syncthreads();
    if (threadIdx.x == 0) g_mask_u8 = found;
}

// ---------------------------------------------------------------------------
// RoPE + split + bf16 hi/lo decomposition. Q scaled by 1/8. V transposed.
// ---------------------------------------------------------------------------
__device__ __forceinline__ void wr_hl(__nv_bfloat16* hi, __nv_bfloat16* lo,
                                      size_t off, float v) {
    __nv_bfloat16 h = __float2bfloat16(v);
    hi[off] = h;
    lo[off] = __float2bfloat16(v - __bfloat162float(h));
}

__global__ __launch_bounds__(256) void rope_scatter(const float* __restrict__ qkv,
                                                    const int* __restrict__ pos_ids) {
    int idx = blockIdx.x * blockDim.x + threadIdx.x;
    int d = idx & 31;
    int h = (idx >> 5) & (NH - 1);
    int s = (idx >> 10) & (SEQ - 1);
    int b = idx >> 21;
    int pos = pos_ids[b * SEQ + s];

    const float* src = qkv + (size_t)(b * SEQ + s) * NQKV + h * (3 * HD);
    float q1 = src[d],       q2 = src[d + 32];
    float k1 = src[64 + d],  k2 = src[96 + d];
    float v1 = src[128 + d], v2 = src[160 + d];

    float invf = (float)pow(10000.0, -(double)d / 32.0);
    float t = (float)pos * invf;
    float sn = (float)sin((double)t);
    float cs = (float)cos((double)t);

    const float qs = 0.125f;
    size_t qk = ((size_t)(b * NH + h) * SEQ + s) * HD;
    wr_hl(g_Qhi, g_Qlo, qk + d,      (q1 * cs - q2 * sn) * qs);
    wr_hl(g_Qhi, g_Qlo, qk + d + 32, (q2 * cs + q1 * sn) * qs);
    wr_hl(g_Khi, g_Klo, qk + d,      k1 * cs - k2 * sn);
    wr_hl(g_Khi, g_Klo, qk + d + 32, k2 * cs + k1 * sn);
    size_t vt = ((size_t)(b * NH + h) * HD + d) * SEQ + s;
    wr_hl(g_Vthi, g_Vtlo, vt,                 v1);
    wr_hl(g_Vthi, g_Vtlo, vt + 32 * SEQ,      v2);
}

// ---------------------------------------------------------------------------
// Flash attention via bf16x3 HMMA. Block = (b, h, 64 q rows), 4 warps x m16.
// SMEM: K hi/lo, Vt hi/lo tiles [64][72] bf16 + mask tile [64][66] float.
// ---------------------------------------------------------------------------
#define FSTR 72
#define BSTR 66
#define FLASH_SMEM (4 * 64 * FSTR * 2 + 64 * BSTR * 4)   // 53760 B

__global__ __launch_bounds__(128) void flash_hmma(const unsigned char* __restrict__ mask,
                                                  float* __restrict__ attn) {
    extern __shared__ char fsm[];
    __nv_bfloat16* sKh = (__nv_bfloat16*)fsm;
    __nv_bfloat16* sKl = sKh + 64 * FSTR;
    __nv_bfloat16* sVh = sKl + 64 * FSTR;
    __nv_bfloat16* sVl = sVh + 64 * FSTR;
    float* sBias = (float*)(sVl + 64 * FSTR);

    const int q0 = blockIdx.x * 64;
    const int h  = blockIdx.y;
    const int b  = blockIdx.z;
    const int tid = threadIdx.x;
    const int wid = tid >> 5;
    const int lane = tid & 31;
    const int mask_u8 = g_mask_u8;

    const size_t hb = (size_t)(b * NH + h) * SEQ;   // rows in [B,H,S,D]
    const size_t vb = (size_t)(b * NH + h) * HD;    // rows in [B,H,D,S]

    const uint32_t uKh = smem_u32(sKh), uKl = smem_u32(sKl);
    const uint32_t uVh = smem_u32(sVh), uVl = smem_u32(sVl);

    const int lrow = tid >> 1;            // 0..63 (load row)
    const int lhalf = (tid & 1) * 32;     // 0 / 32

    // ---- Stage Q tile into sKh/sKl, ldsm Q fragments, then release smem ----
    {
        const __nv_bfloat16* qh_src = g_Qhi + (hb + q0 + lrow) * HD + lhalf;
        const __nv_bfloat16* ql_src = g_Qlo + (hb + q0 + lrow) * HD + lhalf;
        __nv_bfloat16* dh = sKh + lrow * FSTR + lhalf;
        __nv_bfloat16* dl = sKl + lrow * FSTR + lhalf;
#pragma unroll
        for (int j = 0; j < 4; ++j) {
            *(uint4*)(dh + j * 8) = *(const uint4*)(qh_src + j * 8);
            *(uint4*)(dl + j * 8) = *(const uint4*)(ql_src + j * 8);
        }
    }
    __syncthreads();

    const int a_row = lane & 15;
    const int a_col = (lane >> 4) << 3;
    const int b_n   = (lane & 7) + ((lane & 16) ? 8 : 0);
    const int b_k   = (lane & 8) ? 8 : 0;

    uint32_t qh[4][4], ql[4][4];
#pragma unroll
    for (int kc = 0; kc < 4; ++kc) {
        uint32_t off = (uint32_t)(((wid * 16 + a_row) * FSTR + kc * 16 + a_col) * 2);
        ldsm4(uKh + off, qh[kc]);
        ldsm4(uKl + off, ql[kc]);
    }

    const int r0 = lane >> 2;          // fragment row (0..7); r1 = r0 + 8
    const int c2 = (lane & 3) * 2;     // fragment col pair base

    float rm0 = -1e30f, rm1 = -1e30f, l0 = 0.f, l1 = 0.f;
    float o[8][4];
#pragma unroll
    for (int jd = 0; jd < 8; ++jd)
#pragma unroll
        for (int v = 0; v < 4; ++v) o[jd][v] = 0.f;

    for (int k0 = 0; k0 < SEQ; k0 += 64) {
        __syncthreads();   // prior compute (and Q-frag reads) done
        // ---- Load K, Vt, mask tiles ----
        {
            const __nv_bfloat16* kh = g_Khi + (hb + k0 + lrow) * HD + lhalf;
            const __nv_bfloat16* kl = g_Klo + (hb + k0 + lrow) * HD + lhalf;
            const __nv_bfloat16* vh = g_Vthi + (vb + lrow) * SEQ + k0 + lhalf;
            const __nv_bfloat16* vl = g_Vtlo + (vb + lrow) * SEQ + k0 + lhalf;
            __nv_bfloat16* dkh = sKh + lrow * FSTR + lhalf;
            __nv_bfloat16* dkl = sKl + lrow * FSTR + lhalf;
            __nv_bfloat16* dvh = sVh + lrow * FSTR + lhalf;
            __nv_bfloat16* dvl = sVl + lrow * FSTR + lhalf;
#pragma unroll
            for (int j = 0; j < 4; ++j) {
                *(uint4*)(dkh + j * 8) = *(const uint4*)(kh + j * 8);
                *(uint4*)(dkl + j * 8) = *(const uint4*)(kl + j * 8);
                *(uint4*)(dvh + j * 8) = *(const uint4*)(vh + j * 8);
                *(uint4*)(dvl + j * 8) = *(const uint4*)(vl + j * 8);
            }
            float* bdst = sBias + lrow * BSTR + lhalf;
            if (mask_u8) {
                const unsigned char* mp = mask +
                    ((size_t)b * SEQ + q0 + lrow) * SEQ + k0 + lhalf;
                uint4 w0 = *(const uint4*)mp;
                uint4 w1 = *(const uint4*)(mp + 16);
                unsigned a[8] = {w0.x, w0.y, w0.z, w0.w, w1.x, w1.y, w1.z, w1.w};
#pragma unroll
                for (int j = 0; j < 8; ++j) {
                    bdst[j * 4 + 0] = (a[j] & 0x000000FFu) ? 1.f : 0.f;
                    bdst[j * 4 + 1] = (a[j] & 0x0000FF00u) ? 1.f : 0.f;
                    bdst[j * 4 + 2] = (a[j] & 0x00FF0000u) ? 1.f : 0.f;
                    bdst[j * 4 + 3] = (a[j] & 0xFF000000u) ? 1.f : 0.f;
                }
            } else {
                const unsigned* mp = (const unsigned*)mask +
                    ((size_t)b * SEQ + q0 + lrow) * SEQ + k0 + lhalf;
#pragma unroll
                for (int j = 0; j < 8; ++j) {
                    uint4 w = *(const uint4*)(mp + j * 4);
                    bdst[j * 4 + 0] = w.x ? 1.f : 0.f;
                    bdst[j * 4 + 1] = w.y ? 1.f : 0.f;
                    bdst[j * 4 + 2] = w.z ? 1.f : 0.f;
                    bdst[j * 4 + 3] = w.w ? 1.f : 0.f;
                }
            }
        }
        __syncthreads();

        // ---- S = Q K^T (bf16x3) ----
        float sc[8][4];
#pragma unroll
        for (int j = 0; j < 8; ++j)
#pragma unroll
            for (int v = 0; v < 4; ++v) sc[j][v] = 0.f;
#pragma unroll
        for (int jp = 0; jp < 4; ++jp) {          // d chunk (k16)
#pragma unroll
            for (int np = 0; np < 4; ++np) {      // key 16-group
                uint32_t off = (uint32_t)(((np * 16 + b_n) * FSTR + jp * 16 + b_k) * 2);
                uint32_t kh[4], kl[4];
                ldsm4(uKh + off, kh);
                ldsm4(uKl + off, kl);
#pragma unroll
                for (int nt = 0; nt < 2; ++nt) {
                    int j = np * 2 + nt;
                    mma16816(sc[j], qh[jp], kh[nt * 2], kh[nt * 2 + 1]);
                    mma16816(sc[j], ql[jp], kh[nt * 2], kh[nt * 2 + 1]);
                    mma16816(sc[j], qh[jp], kl[nt * 2], kl[nt * 2 + 1]);
                }
            }
        }

        // ---- Mask (replace with -10000) ----
        const float* brow0 = sBias + (wid * 16 + r0) * BSTR;
        const float* brow1 = brow0 + 8 * BSTR;
#pragma unroll
        for (int j = 0; j < 8; ++j) {
            float2 b0 = *(const float2*)(brow0 + j * 8 + c2);
            float2 b1 = *(const float2*)(brow1 + j * 8 + c2);
            if (b0.x != 0.f) sc[j][0] = -10000.f;
            if (b0.y != 0.f) sc[j][1] = -10000.f;
            if (b1.x != 0.f) sc[j][2] = -10000.f;
            if (b1.y != 0.f) sc[j][3] = -10000.f;
        }

        // ---- Online softmax on fragments ----
        float mt0 = -1e30f, mt1 = -1e30f;
#pragma unroll
        for (int j = 0; j < 8; ++j) {
            mt0 = fmaxf(mt0, fmaxf(sc[j][0], sc[j][1]));
            mt1 = fmaxf(mt1, fmaxf(sc[j][2], sc[j][3]));
        }
        mt0 = fmaxf(mt0, __shfl_xor_sync(0xffffffffu, mt0, 1));
        mt0 = fmaxf(mt0, __shfl_xor_sync(0xffffffffu, mt0, 2));
        mt1 = fmaxf(mt1, __shfl_xor_sync(0xffffffffu, mt1, 1));
        mt1 = fmaxf(mt1, __shfl_xor_sync(0xffffffffu, mt1, 2));
        float mn0 = fmaxf(rm0, mt0), cf0 = fexp(rm0 - mn0);
        float mn1 = fmaxf(rm1, mt1), cf1 = fexp(rm1 - mn1);
        rm0 = mn0; rm1 = mn1;

        float rs0 = 0.f, rs1 = 0.f;
#pragma unroll
        for (int j = 0; j < 8; ++j) {
            sc[j][0] = fexp(sc[j][0] - mn0);
            sc[j][1] = fexp(sc[j][1] - mn0);
            sc[j][2] = fexp(sc[j][2] - mn1);
            sc[j][3] = fexp(sc[j][3] - mn1);
            rs0 += sc[j][0] + sc[j][1];
            rs1 += sc[j][2] + sc[j][3];
        }
        rs0 += __shfl_xor_sync(0xffffffffu, rs0, 1);
        rs0 += __shfl_xor_sync(0xffffffffu, rs0, 2);
        rs1 += __shfl_xor_sync(0xffffffffu, rs1, 1);
        rs1 += __shfl_xor_sync(0xffffffffu, rs1, 2);
        l0 = l0 * cf0 + rs0;
        l1 = l1 * cf1 + rs1;

#pragma unroll
        for (int jd = 0; jd < 8; ++jd) {
            o[jd][0] *= cf0; o[jd][1] *= cf0;
            o[jd][2] *= cf1; o[jd][3] *= cf1;
        }

        // ---- P -> A fragments (hi/lo) in registers ----
        uint32_t ph[4][4], pl[4][4];
#pragma unroll
        for (int jp = 0; jp < 4; ++jp) {
            pack3(sc[2 * jp][0],     sc[2 * jp][1],     ph[jp][0], pl[jp][0]);
            pack3(sc[2 * jp][2],     sc[2 * jp][3],     ph[jp][1], pl[jp][1]);
            pack3(sc[2 * jp + 1][0], sc[2 * jp + 1][1], ph[jp][2], pl[jp][2]);
            pack3(sc[2 * jp + 1][2], sc[2 * jp + 1][3], ph[jp][3], pl[jp][3]);
        }

        // ---- O += P V (bf16x3), Vt in smem as [d][key] ----
#pragma unroll
        for (int np = 0; np < 4; ++np) {          // d 16-group
#pragma unroll
            for (int jp = 0; jp < 4; ++jp) {      // key chunk (k16)
                uint32_t off = (uint32_t)(((np * 16 + b_n) * FSTR + jp * 16 + b_k) * 2);
                uint32_t vh[4], vl[4];
                ldsm4(uVh + off, vh);
                ldsm4(uVl + off, vl);
#pragma unroll
                for (int nt = 0; nt < 2; ++nt) {
                    int jd = np * 2 + nt;
                    mma16816(o[jd], ph[jp], vh[nt * 2], vh[nt * 2 + 1]);
                    mma16816(o[jd], pl[jp], vh[nt * 2], vh[nt * 2 + 1]);
                    mma16816(o[jd], ph[jp], vl[nt * 2], vl[nt * 2 + 1]);
                }
            }
        }
    }

    // ---- Epilogue ----
    float i0 = 1.f / l0, i1 = 1.f / l1;
    int qr = q0 + wid * 16 + r0;
#pragma unroll
    for (int jd = 0; jd < 8; ++jd) {
        float2 v0 = make_float2(o[jd][0] * i0, o[jd][1] * i0);
        float2 v1 = make_float2(o[jd][2] * i1, o[jd][3] * i1);
        size_t base = ((size_t)b * SEQ + qr) * HIDD + h * HD + jd * 8 + c2;
        *(float2*)(attn + base) = v0;
        *(float2*)(attn + base + (size_t)8 * HIDD) = v1;
    }
}

// ---------------------------------------------------------------------------
extern "C" void kernel_launch(void* const* d_in, const int* in_sizes, int n_in,
                              void* d_out, int out_size) {
    (void)in_sizes; (void)n_in; (void)out_size;
    const float* hidden        = (const float*)d_in[0];
    const unsigned char* mask  = (const unsigned char*)d_in[1];
    const int* pos             = (const int*)d_in[2];
    const float* Wqkv          = (const float*)d_in[3];
    const float* Wo            = (const float*)d_in[4];
    float* out                 = (float*)d_out;

    float *qkv = nullptr, *attn = nullptr;
    __nv_bfloat16 *xhi, *xlo, *whi, *wlo;
    cudaGetSymbolAddress((void**)&qkv, g_qkv);
    cudaGetSymbolAddress((void**)&attn, g_attn);
    cudaGetSymbolAddress((void**)&xhi, g_xhi);
    cudaGetSymbolAddress((void**)&xlo, g_xlo);
    cudaGetSymbolAddress((void**)&whi, g_whi);
    cudaGetSymbolAddress((void**)&wlo, g_wlo);

    cudaFuncSetAttribute(flash_hmma, cudaFuncAttributeMaxDynamicSharedMemorySize,
                         FLASH_SMEM);

    detect_mask_kernel<<<1, 256>>>(mask);

    // QKV projection
    decompose_kernel<<<(MROWS * HIDD / 4) / 256, 256>>>(
        (const float4*)hidden, (__nv_bfloat162*)xhi, (__nv_bfloat162*)xlo,
        MROWS * HIDD / 4);
    decompose_kernel<<<(NQKV * HIDD / 4) / 256, 256>>>(
        (const float4*)Wqkv, (__nv_bfloat162*)whi, (__nv_bfloat162*)wlo,
        NQKV * HIDD / 4);
    hmma_gemm<<<dim3(NQKV / 128, MROWS / 128), 256>>>(
        xhi, xlo, whi, wlo, qkv, HIDD, NQKV);

    rope_scatter<<<(NB * SEQ * NH * 32) / 256, 256>>>(qkv, pos);

    flash_hmma<<<dim3(SEQ / 64, NH, NB), 128, FLASH_SMEM>>>(mask, attn);

    // O projection
    decompose_kernel<<<(MROWS * HIDD / 4) / 256, 256>>>(
        (const float4*)attn, (__nv_bfloat162*)xhi, (__nv_bfloat162*)xlo,
        MROWS * HIDD / 4);
    decompose_kernel<<<(HIDD * HIDD / 4) / 256, 256>>>(
        (const float4*)Wo, (__nv_bfloat162*)whi, (__nv_bfloat162*)wlo,
        HIDD * HIDD / 4);
    hmma_gemm<<<dim3(HIDD / 128, MROWS / 128), 256>>>(
        xhi, xlo, whi, wlo, out, HIDD, HIDD);
}

// round 14
// speedup vs baseline: 2.0569x; 1.0979x over previous
#include <cuda_runtime.h>
#include <cuda_bf16.h>
#include <math.h>
#include <stdint.h>

#define SEQ   2048
#define NH    32
#define HD    64
#define HIDD  2048
#define NB    2
#define NQKV  (3 * NH * HD)   // 6144
#define MROWS (NB * SEQ)      // 4096

// ---------------------------------------------------------------------------
// Scratch (__device__ globals per harness rules — no cudaMalloc anywhere)
// ---------------------------------------------------------------------------
__device__ float g_qkv[(size_t)MROWS * NQKV];
__device__ int   g_mask_u8;
// GEMM decomposition buffers (x reused: hidden, then attn written by flash)
__device__ __nv_bfloat16 g_xhi[(size_t)MROWS * HIDD];
__device__ __nv_bfloat16 g_xlo[(size_t)MROWS * HIDD];
__device__ __nv_bfloat16 g_whi[(size_t)NQKV * HIDD];
__device__ __nv_bfloat16 g_wlo[(size_t)NQKV * HIDD];
// Attention operands, bf16 hi/lo
__device__ __nv_bfloat16 g_Qhi[(size_t)NB * NH * SEQ * HD];  // [B,H,S,D], scaled 1/8
__device__ __nv_bfloat16 g_Qlo[(size_t)NB * NH * SEQ * HD];
__device__ __nv_bfloat16 g_Khi[(size_t)NB * NH * SEQ * HD];  // [B,H,S,D]
__device__ __nv_bfloat16 g_Klo[(size_t)NB * NH * SEQ * HD];
__device__ __nv_bfloat16 g_Vthi[(size_t)NB * NH * HD * SEQ]; // [B,H,D,S] transposed
__device__ __nv_bfloat16 g_Vtlo[(size_t)NB * NH * HD * SEQ];

// ---------------------------------------------------------------------------
// Warp-MMA helpers (portable PTX: sm_80+)
// ---------------------------------------------------------------------------
__device__ __forceinline__ uint32_t smem_u32(const void* p) {
    uint32_t a;
    asm("{ .reg .u64 t; cvta.to.shared.u64 t, %1; cvt.u32.u64 %0, t; }"
        : "=r"(a) : "l"(p));
    return a;
}

__device__ __forceinline__ void ldsm4(uint32_t addr, uint32_t* r) {
    asm volatile("ldmatrix.sync.aligned.m8n8.x4.shared.b16 {%0,%1,%2,%3}, [%4];"
                 : "=r"(r[0]), "=r"(r[1]), "=r"(r[2]), "=r"(r[3]) : "r"(addr));
}

__device__ __forceinline__ void mma16816(float* c, const uint32_t* a,
                                         uint32_t b0, uint32_t b1) {
    asm volatile(
        "mma.sync.aligned.m16n8k16.row.col.f32.bf16.bf16.f32 "
        "{%0,%1,%2,%3}, {%4,%5,%6,%7}, {%8,%9}, {%0,%1,%2,%3};"
        : "+f"(c[0]), "+f"(c[1]), "+f"(c[2]), "+f"(c[3])
        : "r"(a[0]), "r"(a[1]), "r"(a[2]), "r"(a[3]), "r"(b0), "r"(b1));
}

__device__ __forceinline__ void cp16(uint32_t dst, const void* src) {
    asm volatile("cp.async.cg.shared.global [%0], [%1], 16;"
                 :: "r"(dst), "l"(src));
}

// Fast exp on the FMA pipe. x <= 0; ~1e-7 rel.
__device__ __forceinline__ float fexp(float x) {
    x = fmaxf(x, -80.f);
    float t = fmaf(x, 1.4426950408889634f, 12582912.f);
    float n = t - 12582912.f;
    float f = fmaf(x, 1.4426950408889634f, -n);
    float p = 1.8775767e-3f;
    p = fmaf(p, f, 8.9893397e-3f);
    p = fmaf(p, f, 5.5826318e-2f);
    p = fmaf(p, f, 2.4015361e-1f);
    p = fmaf(p, f, 6.9315308e-1f);
    p = fmaf(p, f, 1.0f);
    return __int_as_float(__float_as_int(p) + (__float_as_int(t) << 23));
}

// float pair -> bf16x2 hi reg + bf16x2 lo reg
__device__ __forceinline__ void pack3(float f0, float f1, uint32_t& rh, uint32_t& rl) {
    __nv_bfloat16 h0 = __float2bfloat16(f0), h1 = __float2bfloat16(f1);
    __nv_bfloat16 l0 = __float2bfloat16(f0 - __bfloat162float(h0));
    __nv_bfloat16 l1 = __float2bfloat16(f1 - __bfloat162float(h1));
    __nv_bfloat162 H = __halves2bfloat162(h0, h1);
    __nv_bfloat162 L = __halves2bfloat162(l0, l1);
    rh = *(uint32_t*)&H;
    rl = *(uint32_t*)&L;
}

// ---------------------------------------------------------------------------
// Decompose fp32 -> bf16 hi + lo
// ---------------------------------------------------------------------------
__global__ __launch_bounds__(256) void decompose_kernel(
        const float4* __restrict__ x, __nv_bfloat162* __restrict__ hi,
        __nv_bfloat162* __restrict__ lo, int n4) {
    int i = blockIdx.x * blockDim.x + threadIdx.x;
    if (i >= n4) return;
    float4 v = x[i];
    __nv_bfloat16 h0 = __float2bfloat16(v.x), h1 = __float2bfloat16(v.y);
    __nv_bfloat16 h2 = __float2bfloat16(v.z), h3 = __float2bfloat16(v.w);
    __nv_bfloat16 l0 = __float2bfloat16(v.x - __bfloat162float(h0));
    __nv_bfloat16 l1 = __float2bfloat16(v.y - __bfloat162float(h1));
    __nv_bfloat16 l2 = __float2bfloat16(v.z - __bfloat162float(h2));
    __nv_bfloat16 l3 = __float2bfloat16(v.w - __bfloat162float(h3));
    hi[2 * i]     = __halves2bfloat162(h0, h1);
    hi[2 * i + 1] = __halves2bfloat162(h2, h3);
    lo[2 * i]     = __halves2bfloat162(l0, l1);
    lo[2 * i + 1] = __halves2bfloat162(l2, l3);
}

// ---------------------------------------------------------------------------
// Projection GEMM: C[m][n] = sum_k A[m][k]*B[n][k], bf16x3 HMMA,
// cp.async 2-stage pipelined smem. 128x128 CTA tile, BK=32, 8 warps.
// Dynamic smem: 2 stages x 4 arrays x 128 x SSTR bf16 = 81920 B.
// ---------------------------------------------------------------------------
#define SSTR 40
#define ARR_B  (128 * SSTR * 2)          // bytes per array (10240)
#define STG_B  (4 * ARR_B)               // bytes per stage (40960)
#define GEMM_SMEM (2 * STG_B)            // 81920

__global__ __launch_bounds__(256, 2) void hmma_gemm(
        const __nv_bfloat16* __restrict__ Ah, const __nv_bfloat16* __restrict__ Al,
        const __nv_bfloat16* __restrict__ Bh, const __nv_bfloat16* __restrict__ Bl,
        float* __restrict__ C, int K, int N) {
    extern __shared__ char gsm[];
    const uint32_t ub = smem_u32(gsm);

    const int tid = threadIdx.x;
    const int wid = tid >> 5;
    const int lane = tid & 31;
    const int warp_m = wid & 1;
    const int warp_n = wid >> 1;
    const int m0 = blockIdx.y * 128, n0 = blockIdx.x * 128;

    const int lr = tid >> 1;
    const int ls = (tid & 1) << 4;
    const __nv_bfloat16* pAh = Ah + (size_t)(m0 + lr) * K + ls;
    const __nv_bfloat16* pAl = Al + (size_t)(m0 + lr) * K + ls;
    const __nv_bfloat16* pBh = Bh + (size_t)(n0 + lr) * K + ls;
    const __nv_bfloat16* pBl = Bl + (size_t)(n0 + lr) * K + ls;
    const uint32_t so = (uint32_t)(lr * SSTR + ls) * 2;   // byte offset in array

    const int a_row = lane & 15;
    const int a_col = (lane >> 4) << 3;
    const int b_n   = (lane & 7) + ((lane & 16) ? 8 : 0);
    const int b_k   = (lane & 8) ? 8 : 0;

    float acc[4][4][4];
#pragma unroll
    for (int i = 0; i < 4; ++i)
#pragma unroll
        for (int j = 0; j < 4; ++j)
#pragma unroll
            for (int v = 0; v < 4; ++v) acc[i][j][v] = 0.f;

    const int kIters = K >> 5;

    // issue stage copies for K-iter `it` into stage `st`
    auto issue = [&](int it, int st) {
        const int k0 = it << 5;
        uint32_t d = ub + st * STG_B + so;
        cp16(d,                pAh + k0);
        cp16(d + 16,           pAh + k0 + 8);
        cp16(d + ARR_B,        pAl + k0);
        cp16(d + ARR_B + 16,   pAl + k0 + 8);
        cp16(d + 2 * ARR_B,      pBh + k0);
        cp16(d + 2 * ARR_B + 16, pBh + k0 + 8);
        cp16(d + 3 * ARR_B,      pBl + k0);
        cp16(d + 3 * ARR_B + 16, pBl + k0 + 8);
        asm volatile("cp.async.commit_group;" ::: "memory");
    };

    issue(0, 0);

    for (int it = 0; it < kIters; ++it) {
        const int st = it & 1;
        if (it + 1 < kIters) {
            issue(it + 1, st ^ 1);
            asm volatile("cp.async.wait_group 1;" ::: "memory");
        } else {
            asm volatile("cp.async.wait_group 0;" ::: "memory");
        }
        __syncthreads();

        const uint32_t uAh = ub + st * STG_B;
        const uint32_t uAl = uAh + ARR_B;
        const uint32_t uBh = uAh + 2 * ARR_B;
        const uint32_t uBl = uAh + 3 * ARR_B;

#pragma unroll
        for (int ks = 0; ks < 2; ++ks) {
            const int kb = ks << 4;
            uint32_t bh[2][4], bl[2][4];
#pragma unroll
            for (int np = 0; np < 2; ++np) {
                uint32_t boff = (uint32_t)(((warp_n * 32 + np * 16 + b_n) * SSTR
                                            + kb + b_k) * 2);
                ldsm4(uBh + boff, bh[np]);
                ldsm4(uBl + boff, bl[np]);
            }
#pragma unroll
            for (int mt = 0; mt < 4; ++mt) {
                uint32_t aoff = (uint32_t)(((warp_m * 64 + mt * 16 + a_row) * SSTR
                                            + kb + a_col) * 2);
                uint32_t ahf[4], alf[4];
                ldsm4(uAh + aoff, ahf);
                ldsm4(uAl + aoff, alf);
#pragma unroll
                for (int nt = 0; nt < 4; ++nt) {
                    uint32_t b0h = bh[nt >> 1][(nt & 1) * 2];
                    uint32_t b1h = bh[nt >> 1][(nt & 1) * 2 + 1];
                    uint32_t b0l = bl[nt >> 1][(nt & 1) * 2];
                    uint32_t b1l = bl[nt >> 1][(nt & 1) * 2 + 1];
                    mma16816(acc[mt][nt], ahf, b0h, b1h);
                    mma16816(acc[mt][nt], alf, b0h, b1h);
                    mma16816(acc[mt][nt], ahf, b0l, b1l);
                }
            }
        }
        __syncthreads();   // reads done before stage st is overwritten
    }

#pragma unroll
    for (int mt = 0; mt < 4; ++mt) {
#pragma unroll
        for (int nt = 0; nt < 4; ++nt) {
            int r = m0 + warp_m * 64 + mt * 16 + (lane >> 2);
            int c = n0 + warp_n * 32 + nt * 8 + (lane & 3) * 2;
            float2 lo = make_float2(acc[mt][nt][0], acc[mt][nt][1]);
            float2 hi = make_float2(acc[mt][nt][2], acc[mt][nt][3]);
            *(float2*)(C + (size_t)r * N + c) = lo;
            *(float2*)(C + (size_t)(r + 8) * N + c) = hi;
        }
    }
}

// ---------------------------------------------------------------------------
// Mask element-width detection (1-byte bool vs 4-byte words)
// ---------------------------------------------------------------------------
__global__ void detect_mask_kernel(const unsigned char* __restrict__ m) {
    __shared__ int found;
    if (threadIdx.x == 0) found = 0;
    __syncthreads();
    const uint4* p = (const uint4*)m;
    int f = 0;
    for (int i = threadIdx.x; i < 65536; i += blockDim.x) {
        uint4 w = p[i];
        unsigned ws[4] = {w.x, w.y, w.z, w.w};
#pragma unroll
        for (int j = 0; j < 4; ++j) {
            unsigned v = ws[j];
            if (((v >> 8) & 0xFFu) == 1u || ((v >> 16) & 0xFFu) == 1u ||
                ((v >> 24) & 0xFFu) == 1u)
                f = 1;
        }
    }
    if (f) atomicOr(&found, 1);
    __syncthreads();
    if (threadIdx.x == 0) g_mask_u8 = found;
}

// ---------------------------------------------------------------------------
// RoPE + split + bf16 hi/lo decomposition. Q scaled by 1/8. V transposed.
// ---------------------------------------------------------------------------
__device__ __forceinline__ void wr_hl(__nv_bfloat16* hi, __nv_bfloat16* lo,
                                      size_t off, float v) {
    __nv_bfloat16 h = __float2bfloat16(v);
    hi[off] = h;
    lo[off] = __float2bfloat16(v - __bfloat162float(h));
}

__global__ __launch_bounds__(256) void rope_scatter(const float* __restrict__ qkv,
                                                    const int* __restrict__ pos_ids) {
    int idx = blockIdx.x * blockDim.x + threadIdx.x;
    int d = idx & 31;
    int h = (idx >> 5) & (NH - 1);
    int s = (idx >> 10) & (SEQ - 1);
    int b = idx >> 21;
    int pos = pos_ids[b * SEQ + s];

    const float* src = qkv + (size_t)(b * SEQ + s) * NQKV + h * (3 * HD);
    float q1 = src[d],       q2 = src[d + 32];
    float k1 = src[64 + d],  k2 = src[96 + d];
    float v1 = src[128 + d], v2 = src[160 + d];

    float invf = (float)pow(10000.0, -(double)d / 32.0);
    float t = (float)pos * invf;
    float sn = (float)sin((double)t);
    float cs = (float)cos((double)t);

    const float qs = 0.125f;
    size_t qk = ((size_t)(b * NH + h) * SEQ + s) * HD;
    wr_hl(g_Qhi, g_Qlo, qk + d,      (q1 * cs - q2 * sn) * qs);
    wr_hl(g_Qhi, g_Qlo, qk + d + 32, (q2 * cs + q1 * sn) * qs);
    wr_hl(g_Khi, g_Klo, qk + d,      k1 * cs - k2 * sn);
    wr_hl(g_Khi, g_Klo, qk + d + 32, k2 * cs + k1 * sn);
    size_t vt = ((size_t)(b * NH + h) * HD + d) * SEQ + s;
    wr_hl(g_Vthi, g_Vtlo, vt,                 v1);
    wr_hl(g_Vthi, g_Vtlo, vt + 32 * SEQ,      v2);
}

// ---------------------------------------------------------------------------
// Flash attention via bf16x3 HMMA. Block = (b, h, 64 q rows), 4 warps x m16.
// Epilogue writes bf16 hi/lo directly into g_xhi/g_xlo (fused decompose).
// ---------------------------------------------------------------------------
#define FSTR 72
#define BSTR 66
#define FLASH_SMEM (4 * 64 * FSTR * 2 + 64 * BSTR * 4)   // 53760 B

__global__ __launch_bounds__(128) void flash_hmma(const unsigned char* __restrict__ mask) {
    extern __shared__ char fsm[];
    __nv_bfloat16* sKh = (__nv_bfloat16*)fsm;
    __nv_bfloat16* sKl = sKh + 64 * FSTR;
    __nv_bfloat16* sVh = sKl + 64 * FSTR;
    __nv_bfloat16* sVl = sVh + 64 * FSTR;
    float* sBias = (float*)(sVl + 64 * FSTR);

    const int q0 = blockIdx.x * 64;
    const int h  = blockIdx.y;
    const int b  = blockIdx.z;
    const int tid = threadIdx.x;
    const int wid = tid >> 5;
    const int lane = tid & 31;
    const int mask_u8 = g_mask_u8;

    const size_t hb = (size_t)(b * NH + h) * SEQ;
    const size_t vb = (size_t)(b * NH + h) * HD;

    const uint32_t uKh = smem_u32(sKh), uKl = smem_u32(sKl);
    const uint32_t uVh = smem_u32(sVh), uVl = smem_u32(sVl);

    const int lrow = tid >> 1;
    const int lhalf = (tid & 1) * 32;

    // ---- Stage Q tile, ldsm Q fragments, release smem ----
    {
        const __nv_bfloat16* qh_src = g_Qhi + (hb + q0 + lrow) * HD + lhalf;
        const __nv_bfloat16* ql_src = g_Qlo + (hb + q0 + lrow) * HD + lhalf;
        __nv_bfloat16* dh = sKh + lrow * FSTR + lhalf;
        __nv_bfloat16* dl = sKl + lrow * FSTR + lhalf;
#pragma unroll
        for (int j = 0; j < 4; ++j) {
            *(uint4*)(dh + j * 8) = *(const uint4*)(qh_src + j * 8);
            *(uint4*)(dl + j * 8) = *(const uint4*)(ql_src + j * 8);
        }
    }
    __syncthreads();

    const int a_row = lane & 15;
    const int a_col = (lane >> 4) << 3;
    const int b_n   = (lane & 7) + ((lane & 16) ? 8 : 0);
    const int b_k   = (lane & 8) ? 8 : 0;

    uint32_t qh[4][4], ql[4][4];
#pragma unroll
    for (int kc = 0; kc < 4; ++kc) {
        uint32_t off = (uint32_t)(((wid * 16 + a_row) * FSTR + kc * 16 + a_col) * 2);
        ldsm4(uKh + off, qh[kc]);
        ldsm4(uKl + off, ql[kc]);
    }

    const int r0 = lane >> 2;
    const int c2 = (lane & 3) * 2;

    float rm0 = -1e30f, rm1 = -1e30f, l0 = 0.f, l1 = 0.f;
    float o[8][4];
#pragma unroll
    for (int jd = 0; jd < 8; ++jd)
#pragma unroll
        for (int v = 0; v < 4; ++v) o[jd][v] = 0.f;

    for (int k0 = 0; k0 < SEQ; k0 += 64) {
        __syncthreads();
        {
            const __nv_bfloat16* kh = g_Khi + (hb + k0 + lrow) * HD + lhalf;
            const __nv_bfloat16* kl = g_Klo + (hb + k0 + lrow) * HD + lhalf;
            const __nv_bfloat16* vh = g_Vthi + (vb + lrow) * SEQ + k0 + lhalf;
            const __nv_bfloat16* vl = g_Vtlo + (vb + lrow) * SEQ + k0 + lhalf;
            __nv_bfloat16* dkh = sKh + lrow * FSTR + lhalf;
            __nv_bfloat16* dkl = sKl + lrow * FSTR + lhalf;
            __nv_bfloat16* dvh = sVh + lrow * FSTR + lhalf;
            __nv_bfloat16* dvl = sVl + lrow * FSTR + lhalf;
#pragma unroll
            for (int j = 0; j < 4; ++j) {
                *(uint4*)(dkh + j * 8) = *(const uint4*)(kh + j * 8);
                *(uint4*)(dkl + j * 8) = *(const uint4*)(kl + j * 8);
                *(uint4*)(dvh + j * 8) = *(const uint4*)(vh + j * 8);
                *(uint4*)(dvl + j * 8) = *(const uint4*)(vl + j * 8);
            }
            float* bdst = sBias + lrow * BSTR + lhalf;
            if (mask_u8) {
                const unsigned char* mp = mask +
                    ((size_t)b * SEQ + q0 + lrow) * SEQ + k0 + lhalf;
                uint4 w0 = *(const uint4*)mp;
                uint4 w1 = *(const uint4*)(mp + 16);
                unsigned a[8] = {w0.x, w0.y, w0.z, w0.w, w1.x, w1.y, w1.z, w1.w};
#pragma unroll
                for (int j = 0; j < 8; ++j) {
                    bdst[j * 4 + 0] = (a[j] & 0x000000FFu) ? 1.f : 0.f;
                    bdst[j * 4 + 1] = (a[j] & 0x0000FF00u) ? 1.f : 0.f;
                    bdst[j * 4 + 2] = (a[j] & 0x00FF0000u) ? 1.f : 0.f;
                    bdst[j * 4 + 3] = (a[j] & 0xFF000000u) ? 1.f : 0.f;
                }
            } else {
                const unsigned* mp = (const unsigned*)mask +
                    ((size_t)b * SEQ + q0 + lrow) * SEQ + k0 + lhalf;
#pragma unroll
                for (int j = 0; j < 8; ++j) {
                    uint4 w = *(const uint4*)(mp + j * 4);
                    bdst[j * 4 + 0] = w.x ? 1.f : 0.f;
                    bdst[j * 4 + 1] = w.y ? 1.f : 0.f;
                    bdst[j * 4 + 2] = w.z ? 1.f : 0.f;
                    bdst[j * 4 + 3] = w.w ? 1.f : 0.f;
                }
            }
        }
        __syncthreads();

        // ---- S = Q K^T (bf16x3) ----
        float sc[8][4];
#pragma unroll
        for (int j = 0; j < 8; ++j)
#pragma unroll
            for (int v = 0; v < 4; ++v) sc[j][v] = 0.f;
#pragma unroll
        for (int jp = 0; jp < 4; ++jp) {
#pragma unroll
            for (int np = 0; np < 4; ++np) {
                uint32_t off = (uint32_t)(((np * 16 + b_n) * FSTR + jp * 16 + b_k) * 2);
                uint32_t kh[4], kl[4];
                ldsm4(uKh + off, kh);
                ldsm4(uKl + off, kl);
#pragma unroll
                for (int nt = 0; nt < 2; ++nt) {
                    int j = np * 2 + nt;
                    mma16816(sc[j], qh[jp], kh[nt * 2], kh[nt * 2 + 1]);
                    mma16816(sc[j], ql[jp], kh[nt * 2], kh[nt * 2 + 1]);
                    mma16816(sc[j], qh[jp], kl[nt * 2], kl[nt * 2 + 1]);
                }
            }
        }

        // ---- Mask ----
        const float* brow0 = sBias + (wid * 16 + r0) * BSTR;
        const float* brow1 = brow0 + 8 * BSTR;
#pragma unroll
        for (int j = 0; j < 8; ++j) {
            float2 b0 = *(const float2*)(brow0 + j * 8 + c2);
            float2 b1 = *(const float2*)(brow1 + j * 8 + c2);
            if (b0.x != 0.f) sc[j][0] = -10000.f;
            if (b0.y != 0.f) sc[j][1] = -10000.f;
            if (b1.x != 0.f) sc[j][2] = -10000.f;
            if (b1.y != 0.f) sc[j][3] = -10000.f;
        }

        // ---- Online softmax ----
        float mt0 = -1e30f, mt1 = -1e30f;
#pragma unroll
        for (int j = 0; j < 8; ++j) {
            mt0 = fmaxf(mt0, fmaxf(sc[j][0], sc[j][1]));
            mt1 = fmaxf(mt1, fmaxf(sc[j][2], sc[j][3]));
        }
        mt0 = fmaxf(mt0, __shfl_xor_sync(0xffffffffu, mt0, 1));
        mt0 = fmaxf(mt0, __shfl_xor_sync(0xffffffffu, mt0, 2));
        mt1 = fmaxf(mt1, __shfl_xor_sync(0xffffffffu, mt1, 1));
        mt1 = fmaxf(mt1, __shfl_xor_sync(0xffffffffu, mt1, 2));
        float mn0 = fmaxf(rm0, mt0), cf0 = fexp(rm0 - mn0);
        float mn1 = fmaxf(rm1, mt1), cf1 = fexp(rm1 - mn1);
        rm0 = mn0; rm1 = mn1;

        float rs0 = 0.f, rs1 = 0.f;
#pragma unroll
        for (int j = 0; j < 8; ++j) {
            sc[j][0] = fexp(sc[j][0] - mn0);
            sc[j][1] = fexp(sc[j][1] - mn0);
            sc[j][2] = fexp(sc[j][2] - mn1);
            sc[j][3] = fexp(sc[j][3] - mn1);
            rs0 += sc[j][0] + sc[j][1];
            rs1 += sc[j][2] + sc[j][3];
        }
        rs0 += __shfl_xor_sync(0xffffffffu, rs0, 1);
        rs0 += __shfl_xor_sync(0xffffffffu, rs0, 2);
        rs1 += __shfl_xor_sync(0xffffffffu, rs1, 1);
        rs1 += __shfl_xor_sync(0xffffffffu, rs1, 2);
        l0 = l0 * cf0 + rs0;
        l1 = l1 * cf1 + rs1;

#pragma unroll
        for (int jd = 0; jd < 8; ++jd) {
            o[jd][0] *= cf0; o[jd][1] *= cf0;
            o[jd][2] *= cf1; o[jd][3] *= cf1;
        }

        // ---- P -> A fragments in registers ----
        uint32_t ph[4][4], pl[4][4];
#pragma unroll
        for (int jp = 0; jp < 4; ++jp) {
            pack3(sc[2 * jp][0],     sc[2 * jp][1],     ph[jp][0], pl[jp][0]);
            pack3(sc[2 * jp][2],     sc[2 * jp][3],     ph[jp][1], pl[jp][1]);
            pack3(sc[2 * jp + 1][0], sc[2 * jp + 1][1], ph[jp][2], pl[jp][2]);
            pack3(sc[2 * jp + 1][2], sc[2 * jp + 1][3], ph[jp][3], pl[jp][3]);
        }

        // ---- O += P V (bf16x3) ----
#pragma unroll
        for (int np = 0; np < 4; ++np) {
#pragma unroll
            for (int jp = 0; jp < 4; ++jp) {
                uint32_t off = (uint32_t)(((np * 16 + b_n) * FSTR + jp * 16 + b_k) * 2);
                uint32_t vh[4], vl[4];
                ldsm4(uVh + off, vh);
                ldsm4(uVl + off, vl);
#pragma unroll
                for (int nt = 0; nt < 2; ++nt) {
                    int jd = np * 2 + nt;
                    mma16816(o[jd], ph[jp], vh[nt * 2], vh[nt * 2 + 1]);
                    mma16816(o[jd], pl[jp], vh[nt * 2], vh[nt * 2 + 1]);
                    mma16816(o[jd], ph[jp], vl[nt * 2], vl[nt * 2 + 1]);
                }
            }
        }
    }

    // ---- Epilogue: write bf16 hi/lo directly (fused decompose) ----
    float i0 = 1.f / l0, i1 = 1.f / l1;
    int qr = q0 + wid * 16 + r0;
#pragma unroll
    for (int jd = 0; jd < 8; ++jd) {
        uint32_t h01, l01, h23, l23;
        pack3(o[jd][0] * i0, o[jd][1] * i0, h01, l01);
        pack3(o[jd][2] * i1, o[jd][3] * i1, h23, l23);
        size_t base0 = ((size_t)b * SEQ + qr) * HIDD + h * HD + jd * 8 + c2;
        size_t base1 = base0 + (size_t)8 * HIDD;
        *(uint32_t*)&g_xhi[base0] = h01;
        *(uint32_t*)&g_xlo[base0] = l01;
        *(uint32_t*)&g_xhi[base1] = h23;
        *(uint32_t*)&g_xlo[base1] = l23;
    }
}

// ---------------------------------------------------------------------------
extern "C" void kernel_launch(void* const* d_in, const int* in_sizes, int n_in,
                              void* d_out, int out_size) {
    (void)in_sizes; (void)n_in; (void)out_size;
    const float* hidden        = (const float*)d_in[0];
    const unsigned char* mask  = (const unsigned char*)d_in[1];
    const int* pos             = (const int*)d_in[2];
    const float* Wqkv          = (const float*)d_in[3];
    const float* Wo            = (const float*)d_in[4];
    float* out                 = (float*)d_out;

    float* qkv = nullptr;
    __nv_bfloat16 *xhi, *xlo, *whi, *wlo;
    cudaGetSymbolAddress((void**)&qkv, g_qkv);
    cudaGetSymbolAddress((void**)&xhi, g_xhi);
    cudaGetSymbolAddress((void**)&xlo, g_xlo);
    cudaGetSymbolAddress((void**)&whi, g_whi);
    cudaGetSymbolAddress((void**)&wlo, g_wlo);

    cudaFuncSetAttribute(flash_hmma, cudaFuncAttributeMaxDynamicSharedMemorySize,
                         FLASH_SMEM);
    cudaFuncSetAttribute(hmma_gemm, cudaFuncAttributeMaxDynamicSharedMemorySize,
                         GEMM_SMEM);

    detect_mask_kernel<<<1, 256>>>(mask);

    // QKV projection
    decompose_kernel<<<(MROWS * HIDD / 4) / 256, 256>>>(
        (const float4*)hidden, (__nv_bfloat162*)xhi, (__nv_bfloat162*)xlo,
        MROWS * HIDD / 4);
    decompose_kernel<<<(NQKV * HIDD / 4) / 256, 256>>>(
        (const float4*)Wqkv, (__nv_bfloat162*)whi, (__nv_bfloat162*)wlo,
        NQKV * HIDD / 4);
    hmma_gemm<<<dim3(NQKV / 128, MROWS / 128), 256, GEMM_SMEM>>>(
        xhi, xlo, whi, wlo, qkv, HIDD, NQKV);

    rope_scatter<<<(NB * SEQ * NH * 32) / 256, 256>>>(qkv, pos);

    // Flash writes x hi/lo directly (fused decompose of attn)
    flash_hmma<<<dim3(SEQ / 64, NH, NB), 128, FLASH_SMEM>>>(mask);

    // O projection
    decompose_kernel<<<(HIDD * HIDD / 4) / 256, 256>>>(
        (const float4*)Wo, (__nv_bfloat162*)whi, (__nv_bfloat162*)wlo,
        HIDD * HIDD / 4);
    hmma_gemm<<<dim3(HIDD / 128, MROWS / 128), 256, GEMM_SMEM>>>(
        xhi, xlo, whi, wlo, out, HIDD, HIDD);
}